// round 1
// baseline (speedup 1.0000x reference)
#include <cuda_runtime.h>
#include <math.h>

#define T 2048
#define H 2048
#define E 32
#define KSEL 6
#define G 8
#define TOPKG 4
#define II 1408
#define IS 2816
#define SCALEF 2.5f
#define NA (T*KSEL)   // 12288 assignments

// ---------------- scratch (allocation-free: __device__ globals) ----------------
__device__ float g_topk_w[NA];
__device__ int   g_topk_id[NA];
__device__ int   g_cnt[E];
__device__ int   g_off[E];
__device__ int   g_cur[E];
__device__ int   g_alist[NA];
__device__ float g_h[(size_t)NA * II];   // ~69 MB
__device__ float g_y[(size_t)NA * H];    // ~101 MB
__device__ float g_sh[(size_t)T * IS];   // ~23 MB

// ---------------- small kernels ----------------
__global__ void reset_kernel() {
    if (threadIdx.x < E) g_cnt[threadIdx.x] = 0;
}

__global__ void router_kernel(const float* __restrict__ x,
                              const float* __restrict__ gw,
                              const float* __restrict__ gb) {
    int t = blockIdx.x;
    __shared__ float xs[H];
    __shared__ float logit[E];
    for (int i = threadIdx.x; i < H; i += blockDim.x) xs[i] = x[(size_t)t * H + i];
    __syncthreads();
    int warp = threadIdx.x >> 5, lane = threadIdx.x & 31;
    for (int e = warp; e < E; e += 4) {
        const float* w = gw + (size_t)e * H;
        float s = 0.f;
        for (int i = lane; i < H; i += 32) s += xs[i] * w[i];
        #pragma unroll
        for (int o = 16; o; o >>= 1) s += __shfl_xor_sync(0xffffffffu, s, o);
        if (lane == 0) logit[e] = s;
    }
    __syncthreads();
    if (threadIdx.x == 0) {
        float sc[E], ss[E];
        #pragma unroll
        for (int e = 0; e < E; e++) {
            float s = 1.f / (1.f + expf(-logit[e]));
            ss[e] = s;
            sc[e] = s + gb[e];
        }
        float gsc[G];
        #pragma unroll
        for (int g = 0; g < G; g++) {
            float m1 = -1e30f, m2 = -1e30f;
            #pragma unroll
            for (int j = 0; j < 4; j++) {
                float v = sc[g * 4 + j];
                if (v > m1) { m2 = m1; m1 = v; } else if (v > m2) m2 = v;
            }
            gsc[g] = m1 + m2;
        }
        bool gsel[G];
        #pragma unroll
        for (int g = 0; g < G; g++) gsel[g] = false;
        for (int r = 0; r < TOPKG; r++) {
            int best = -1; float bv = -1e30f;
            for (int g = 0; g < G; g++)
                if (!gsel[g] && gsc[g] > bv) { bv = gsc[g]; best = g; }
            gsel[best] = true;
        }
        bool esel[E];
        #pragma unroll
        for (int e = 0; e < E; e++) esel[e] = false;
        int ids[KSEL];
        for (int r = 0; r < KSEL; r++) {
            int best = -1; float bv = -1e30f;
            for (int e = 0; e < E; e++) {
                if (esel[e] || !gsel[e >> 2]) continue;
                if (sc[e] > bv) { bv = sc[e]; best = e; }
            }
            esel[best] = true; ids[r] = best;
        }
        float w[KSEL], wsum = 0.f;
        for (int r = 0; r < KSEL; r++) { w[r] = ss[ids[r]]; wsum += w[r]; }
        float inv = 1.f / wsum;
        for (int r = 0; r < KSEL; r++) {
            g_topk_w[t * KSEL + r] = w[r] * inv;
            g_topk_id[t * KSEL + r] = ids[r];
            atomicAdd(&g_cnt[ids[r]], 1);
        }
    }
}

__global__ void scan_kernel() {
    if (threadIdx.x == 0) {
        int run = 0;
        for (int e = 0; e < E; e++) {
            g_off[e] = run;
            g_cur[e] = run;
            run += g_cnt[e];
        }
    }
}

__global__ void fill_kernel() {
    int a = blockIdx.x * blockDim.x + threadIdx.x;
    if (a >= NA) return;
    int e = g_topk_id[a];
    int pos = atomicAdd(&g_cur[e], 1);
    g_alist[pos] = a;
}

// ---------------- GEMM 1: gate_up + silu*mul ----------------
// ROUTED: per-expert (blockIdx.z) gathered rows from g_alist; W=w1[e] [H,2*II]; out g_h (weighted)
// !ROUTED: all T tokens; W=sw1 [H,2*IS]; out g_sh
template<bool ROUTED>
__global__ void __launch_bounds__(256)
gemm1_kernel(const float* __restrict__ X, const float* __restrict__ W) {
    const int NCOLS = ROUTED ? II : IS;
    const int LDW = 2 * NCOLS;
    int n, off = 0;
    const float* Wb;
    if (ROUTED) {
        int e = blockIdx.z;
        n = g_cnt[e]; off = g_off[e];
        if ((int)(blockIdx.y * 64) >= n) return;
        Wb = W + (size_t)e * H * 2 * II;
    } else {
        n = T; Wb = W;
    }
    int row0 = blockIdx.y * 64;
    int col0 = blockIdx.x * 64;

    __shared__ float As[16][68];
    __shared__ float Bg[16][64];
    __shared__ float Bu[16][64];

    int tid = threadIdx.x;
    int tx = tid & 15, ty = tid >> 4;
    int ar = tid >> 2, ac = tid & 3;
    int br = tid >> 4, bc = tid & 15;

    const float* arow = nullptr;
    if (ROUTED) {
        int gr = row0 + ar;
        if (gr < n) {
            int a = g_alist[off + gr];
            int t = a / KSEL;
            arow = X + (size_t)t * H;
        }
    } else {
        arow = X + (size_t)(row0 + ar) * H;
    }

    float cg[4][4] = {}, cu[4][4] = {};

    for (int k0 = 0; k0 < H; k0 += 16) {
        float4 av = make_float4(0.f, 0.f, 0.f, 0.f);
        if (arow) av = *(const float4*)(arow + k0 + ac * 4);
        As[ac * 4 + 0][ar] = av.x;
        As[ac * 4 + 1][ar] = av.y;
        As[ac * 4 + 2][ar] = av.z;
        As[ac * 4 + 3][ar] = av.w;
        const float* wr = Wb + (size_t)(k0 + br) * LDW;
        *(float4*)&Bg[br][bc * 4] = *(const float4*)(wr + col0 + bc * 4);
        *(float4*)&Bu[br][bc * 4] = *(const float4*)(wr + NCOLS + col0 + bc * 4);
        __syncthreads();
        #pragma unroll
        for (int kk = 0; kk < 16; kk++) {
            float4 a4 = *(const float4*)&As[kk][ty * 4];
            float4 g4 = *(const float4*)&Bg[kk][tx * 4];
            float4 u4 = *(const float4*)&Bu[kk][tx * 4];
            float aa[4] = {a4.x, a4.y, a4.z, a4.w};
            float gg[4] = {g4.x, g4.y, g4.z, g4.w};
            float uu[4] = {u4.x, u4.y, u4.z, u4.w};
            #pragma unroll
            for (int i = 0; i < 4; i++)
                #pragma unroll
                for (int j = 0; j < 4; j++) {
                    cg[i][j] += aa[i] * gg[j];
                    cu[i][j] += aa[i] * uu[j];
                }
        }
        __syncthreads();
    }

    #pragma unroll
    for (int i = 0; i < 4; i++) {
        int r = row0 + ty * 4 + i;
        if (ROUTED) {
            if (r >= n) continue;
            int a = g_alist[off + r];
            float wt = g_topk_w[a];
            float* hrow = g_h + (size_t)a * II + col0;
            #pragma unroll
            for (int j = 0; j < 4; j++) {
                float gv = cg[i][j], uv = cu[i][j];
                float s = gv / (1.f + expf(-gv));
                hrow[tx * 4 + j] = s * uv * wt;
            }
        } else {
            float* hrow = g_sh + (size_t)r * IS + col0;
            #pragma unroll
            for (int j = 0; j < 4; j++) {
                float gv = cg[i][j], uv = cu[i][j];
                float s = gv / (1.f + expf(-gv));
                hrow[tx * 4 + j] = s * uv;
            }
        }
    }
}

// ---------------- GEMM 2: down projection ----------------
// ROUTED: A=g_h rows (gathered), W=w2[e] [II,H], out g_y[a,H]
// !ROUTED: A=g_sh [T,IS], W=sw2 [IS,H], out d_out [T,H]
template<bool ROUTED>
__global__ void __launch_bounds__(256)
gemm2_kernel(const float* __restrict__ W, float* __restrict__ Out) {
    const int KD = ROUTED ? II : IS;
    int n, off = 0;
    const float* Wb;
    if (ROUTED) {
        int e = blockIdx.z;
        n = g_cnt[e]; off = g_off[e];
        if ((int)(blockIdx.y * 64) >= n) return;
        Wb = W + (size_t)e * II * H;
    } else {
        n = T; Wb = W;
    }
    int row0 = blockIdx.y * 64;
    int col0 = blockIdx.x * 64;

    __shared__ float As[16][68];
    __shared__ float Bs[16][64];

    int tid = threadIdx.x;
    int tx = tid & 15, ty = tid >> 4;
    int ar = tid >> 2, ac = tid & 3;
    int br = tid >> 4, bc = tid & 15;

    const float* arow = nullptr;
    if (ROUTED) {
        int gr = row0 + ar;
        if (gr < n) {
            int a = g_alist[off + gr];
            arow = g_h + (size_t)a * II;
        }
    } else {
        arow = g_sh + (size_t)(row0 + ar) * IS;
    }

    float c[4][4] = {};

    for (int k0 = 0; k0 < KD; k0 += 16) {
        float4 av = make_float4(0.f, 0.f, 0.f, 0.f);
        if (arow) av = *(const float4*)(arow + k0 + ac * 4);
        As[ac * 4 + 0][ar] = av.x;
        As[ac * 4 + 1][ar] = av.y;
        As[ac * 4 + 2][ar] = av.z;
        As[ac * 4 + 3][ar] = av.w;
        const float* wr = Wb + (size_t)(k0 + br) * H;
        *(float4*)&Bs[br][bc * 4] = *(const float4*)(wr + col0 + bc * 4);
        __syncthreads();
        #pragma unroll
        for (int kk = 0; kk < 16; kk++) {
            float4 a4 = *(const float4*)&As[kk][ty * 4];
            float4 b4 = *(const float4*)&Bs[kk][tx * 4];
            float aa[4] = {a4.x, a4.y, a4.z, a4.w};
            float bb[4] = {b4.x, b4.y, b4.z, b4.w};
            #pragma unroll
            for (int i = 0; i < 4; i++)
                #pragma unroll
                for (int j = 0; j < 4; j++)
                    c[i][j] += aa[i] * bb[j];
        }
        __syncthreads();
    }

    #pragma unroll
    for (int i = 0; i < 4; i++) {
        int r = row0 + ty * 4 + i;
        if (ROUTED) {
            if (r >= n) continue;
            int a = g_alist[off + r];
            float* yrow = g_y + (size_t)a * H + col0;
            #pragma unroll
            for (int j = 0; j < 4; j++) yrow[tx * 4 + j] = c[i][j];
        } else {
            float* orow = Out + (size_t)r * H + col0;
            #pragma unroll
            for (int j = 0; j < 4; j++) orow[tx * 4 + j] = c[i][j];
        }
    }
}

// ---------------- combine: out += SCALE * sum_k y ----------------
__global__ void combine_kernel(float* __restrict__ out) {
    int idx = blockIdx.x * blockDim.x + threadIdx.x;  // over T*H/4 float4s
    if (idx >= (T * H) / 4) return;
    int t = idx / (H / 4);
    int c4 = idx % (H / 4);
    float4 acc = make_float4(0.f, 0.f, 0.f, 0.f);
    #pragma unroll
    for (int k = 0; k < KSEL; k++) {
        const float4 v = *(const float4*)(g_y + (size_t)(t * KSEL + k) * H + c4 * 4);
        acc.x += v.x; acc.y += v.y; acc.z += v.z; acc.w += v.w;
    }
    float4* o = (float4*)(out + (size_t)t * H + c4 * 4);
    float4 cur = *o;
    cur.x += SCALEF * acc.x;
    cur.y += SCALEF * acc.y;
    cur.z += SCALEF * acc.z;
    cur.w += SCALEF * acc.w;
    *o = cur;
}

// ---------------- launch ----------------
extern "C" void kernel_launch(void* const* d_in, const int* in_sizes, int n_in,
                              void* d_out, int out_size) {
    const float* x   = (const float*)d_in[0];
    const float* gw  = (const float*)d_in[1];
    const float* gb  = (const float*)d_in[2];
    const float* w1  = (const float*)d_in[3];
    const float* w2  = (const float*)d_in[4];
    const float* sw1 = (const float*)d_in[5];
    const float* sw2 = (const float*)d_in[6];
    float* out = (float*)d_out;

    reset_kernel<<<1, 32>>>();
    router_kernel<<<T, 128>>>(x, gw, gb);
    scan_kernel<<<1, 32>>>();
    fill_kernel<<<(NA + 255) / 256, 256>>>();

    // shared expert
    gemm1_kernel<false><<<dim3(IS / 64, T / 64, 1), 256>>>(x, sw1);
    gemm2_kernel<false><<<dim3(H / 64, T / 64, 1), 256>>>(sw2, out);

    // routed experts (grouped)
    gemm1_kernel<true><<<dim3(II / 64, T / 64, E), 256>>>(x, w1);
    gemm2_kernel<true><<<dim3(H / 64, T / 64, E), 256>>>(w2, nullptr);

    combine_kernel<<<((T * H / 4) + 255) / 256, 256>>>(out);
}

// round 3
// speedup vs baseline: 1.7478x; 1.7478x over previous
#include <cuda_runtime.h>
#include <math.h>
#include <stdint.h>

#define T 2048
#define H 2048
#define E 32
#define KSEL 6
#define G 8
#define TOPKG 4
#define II 1408
#define IS 2816
#define SCALEF 2.5f
#define NA (T*KSEL)   // 12288 assignments

// ---------------- scratch (allocation-free: __device__ globals) ----------------
__device__ float g_topk_w[NA];
__device__ int   g_topk_id[NA];
__device__ int   g_cnt[E];
__device__ int   g_off[E];
__device__ int   g_cur[E];
__device__ int   g_alist[NA];
__device__ float g_gu[(size_t)NA * 2 * II];   // routed gate|up  ~138 MB
__device__ float g_h[(size_t)NA * II];        // routed hidden   ~69 MB
__device__ float g_y[(size_t)NA * H];         // routed out      ~101 MB
__device__ float g_sgu[(size_t)T * 2 * IS];   // shared gate|up  ~46 MB
__device__ float g_shh[(size_t)T * IS];       // shared hidden   ~23 MB

// ---------------- helpers ----------------
__device__ __forceinline__ uint32_t f2tf(float f) {
    uint32_t r;
    asm("cvt.rna.tf32.f32 %0, %1;" : "=r"(r) : "f"(f));
    return r;
}
__device__ __forceinline__ void mma8(float* d, const uint32_t* a, const uint32_t* b) {
    asm volatile(
        "mma.sync.aligned.m16n8k8.row.col.f32.tf32.tf32.f32 "
        "{%0,%1,%2,%3}, {%4,%5,%6,%7}, {%8,%9}, {%0,%1,%2,%3};"
        : "+f"(d[0]), "+f"(d[1]), "+f"(d[2]), "+f"(d[3])
        : "r"(a[0]), "r"(a[1]), "r"(a[2]), "r"(a[3]), "r"(b[0]), "r"(b[1]));
}

// ---------------- small kernels ----------------
__global__ void reset_kernel() {
    if (threadIdx.x < E) g_cnt[threadIdx.x] = 0;
}

__global__ void router_kernel(const float* __restrict__ x,
                              const float* __restrict__ gw,
                              const float* __restrict__ gb) {
    int t = blockIdx.x;
    __shared__ float xs[H];
    __shared__ float logit[E];
    for (int i = threadIdx.x; i < H; i += blockDim.x) xs[i] = x[(size_t)t * H + i];
    __syncthreads();
    int warp = threadIdx.x >> 5, lane = threadIdx.x & 31;
    for (int e = warp; e < E; e += 4) {
        const float* w = gw + (size_t)e * H;
        float s = 0.f;
        for (int i = lane; i < H; i += 32) s += xs[i] * w[i];
        #pragma unroll
        for (int o = 16; o; o >>= 1) s += __shfl_xor_sync(0xffffffffu, s, o);
        if (lane == 0) logit[e] = s;
    }
    __syncthreads();
    if (threadIdx.x == 0) {
        float sc[E], ss[E];
        #pragma unroll
        for (int e = 0; e < E; e++) {
            float s = 1.f / (1.f + expf(-logit[e]));
            ss[e] = s;
            sc[e] = s + gb[e];
        }
        float gsc[G];
        #pragma unroll
        for (int g = 0; g < G; g++) {
            float m1 = -1e30f, m2 = -1e30f;
            #pragma unroll
            for (int j = 0; j < 4; j++) {
                float v = sc[g * 4 + j];
                if (v > m1) { m2 = m1; m1 = v; } else if (v > m2) m2 = v;
            }
            gsc[g] = m1 + m2;
        }
        bool gsel[G];
        #pragma unroll
        for (int g = 0; g < G; g++) gsel[g] = false;
        for (int r = 0; r < TOPKG; r++) {
            int best = -1; float bv = -1e30f;
            for (int g = 0; g < G; g++)
                if (!gsel[g] && gsc[g] > bv) { bv = gsc[g]; best = g; }
            gsel[best] = true;
        }
        bool esel[E];
        #pragma unroll
        for (int e = 0; e < E; e++) esel[e] = false;
        int ids[KSEL];
        for (int r = 0; r < KSEL; r++) {
            int best = -1; float bv = -1e30f;
            for (int e = 0; e < E; e++) {
                if (esel[e] || !gsel[e >> 2]) continue;
                if (sc[e] > bv) { bv = sc[e]; best = e; }
            }
            esel[best] = true; ids[r] = best;
        }
        float w[KSEL], wsum = 0.f;
        for (int r = 0; r < KSEL; r++) { w[r] = ss[ids[r]]; wsum += w[r]; }
        float inv = 1.f / wsum;
        for (int r = 0; r < KSEL; r++) {
            g_topk_w[t * KSEL + r] = w[r] * inv;
            g_topk_id[t * KSEL + r] = ids[r];
            atomicAdd(&g_cnt[ids[r]], 1);
        }
    }
}

__global__ void scan_kernel() {
    if (threadIdx.x == 0) {
        int run = 0;
        for (int e = 0; e < E; e++) {
            g_off[e] = run;
            g_cur[e] = run;
            run += g_cnt[e];
        }
    }
}

__global__ void fill_kernel() {
    int a = blockIdx.x * blockDim.x + threadIdx.x;
    if (a >= NA) return;
    int e = g_topk_id[a];
    int pos = atomicAdd(&g_cur[e], 1);
    g_alist[pos] = a;
}

// ---------------- tensor-core tf32 GEMM (mma.sync m16n8k8) ----------------
// 128x128 block tile, K-chunk 32, 8 warps (2x4), warp tile 64x32.
// MODE 0: shared gate_up : A = x[t] (K=H),      B = sw1 (N=2*IS), D = g_sgu
// MODE 1: shared down    : A = g_shh[t] (K=IS), B = sw2 (N=H),    D = out
// MODE 2: routed gate_up : A = x[a/K] (K=H),    B = w1[e] (N=2*II), D = g_gu (row a)
// MODE 3: routed down    : A = g_h[a] (K=II),   B = w2[e] (N=H),    D = g_y (row a)
#define SMEM_GEMM 73216

template<int MODE>
__global__ void __launch_bounds__(256, 1)
gemm_tc(const float* __restrict__ X, const float* __restrict__ W, float* __restrict__ Dout)
{
    constexpr bool ROUTED = (MODE >= 2);
    constexpr int KTOT = (MODE == 0) ? H : (MODE == 1) ? IS : (MODE == 2) ? H : II;
    constexpr int LDB  = (MODE == 0) ? 2 * IS : (MODE == 1) ? H : (MODE == 2) ? 2 * II : H;
    constexpr int NC   = KTOT / 32;

    extern __shared__ float sm[];
    float* Ast[2] = { sm, sm + 128 * 36 };
    float* Bst[2] = { sm + 2 * 128 * 36, sm + 2 * 128 * 36 + 32 * 136 };
    float* meta = sm + 2 * 128 * 36 + 2 * 32 * 136;
    const float** rowptr = (const float**)meta;        // 128 entries (1024 B)
    int* aidx = (int*)(meta + 256);                    // 128 entries

    int n, off = 0;
    const float* Bb = W;
    if (ROUTED) {
        int e = blockIdx.z;
        n = g_cnt[e]; off = g_off[e];
        if ((int)(blockIdx.y * 128) >= n) return;
        Bb = W + (size_t)e * (size_t)KTOT * LDB;
    } else n = T;

    const int row0 = blockIdx.y * 128;
    const int col0 = blockIdx.x * 128;
    const int tid = threadIdx.x;

    if (tid < 128) {
        int gr = row0 + tid;
        int a = -1;
        const float* p;
        if (MODE == 0)      p = X + (size_t)gr * H;
        else if (MODE == 1) p = g_shh + (size_t)gr * IS;
        else {
            if (gr < n) a = g_alist[off + gr];
            int aa = (a >= 0) ? a : g_alist[off];
            if (MODE == 2) p = X + (size_t)(aa / KSEL) * H;
            else           p = g_h + (size_t)aa * II;
        }
        rowptr[tid] = p;
        aidx[tid] = a;
    }
    __syncthreads();

    float* Dbase = (MODE == 1) ? Dout : (MODE == 0 ? g_sgu : (MODE == 2 ? g_gu : g_y));

    const int lane = tid & 31, wid = tid >> 5;
    const int wm = wid >> 2, wn = wid & 3;
    const int gg = lane >> 2, t4 = lane & 3;

    float4 aR[4], bR[4];
    float acc[4][4][4] = {};

    // ---- fill helpers ----
    auto ldg = [&](int k0) {
        #pragma unroll
        for (int r = 0; r < 4; r++) {
            int u = tid + 256 * r;
            aR[r] = *(const float4*)(rowptr[u >> 3] + k0 + (u & 7) * 4);
        }
        #pragma unroll
        for (int r = 0; r < 4; r++) {
            int u = tid + 256 * r;
            int k = u >> 5, nq = u & 31;
            bR[r] = *(const float4*)(Bb + (size_t)(k0 + k) * LDB + col0 + nq * 4);
        }
    };
    auto sts = [&](int s) {
        float* A_ = Ast[s];
        float* B_ = Bst[s];
        #pragma unroll
        for (int r = 0; r < 4; r++) {
            int u = tid + 256 * r;
            uint4 v = make_uint4(f2tf(aR[r].x), f2tf(aR[r].y), f2tf(aR[r].z), f2tf(aR[r].w));
            *(uint4*)(A_ + (u >> 3) * 36 + (u & 7) * 4) = v;
        }
        #pragma unroll
        for (int r = 0; r < 4; r++) {
            int u = tid + 256 * r;
            int k = u >> 5, nq = u & 31;
            uint4 v = make_uint4(f2tf(bR[r].x), f2tf(bR[r].y), f2tf(bR[r].z), f2tf(bR[r].w));
            *(uint4*)(B_ + k * 136 + nq * 4) = v;
        }
    };
    auto comp = [&](int s) {
        const float* A_ = Ast[s];
        const float* B_ = Bst[s];
        #pragma unroll
        for (int kt = 0; kt < 4; kt++) {
            uint32_t af[4][4];
            #pragma unroll
            for (int mt = 0; mt < 4; mt++) {
                int row = wm * 64 + mt * 16 + gg;
                int col = kt * 8 + t4;
                af[mt][0] = __float_as_uint(A_[row * 36 + col]);
                af[mt][1] = __float_as_uint(A_[(row + 8) * 36 + col]);
                af[mt][2] = __float_as_uint(A_[row * 36 + col + 4]);
                af[mt][3] = __float_as_uint(A_[(row + 8) * 36 + col + 4]);
            }
            uint32_t bf[4][2];
            #pragma unroll
            for (int nt = 0; nt < 4; nt++) {
                int cb = wn * 32 + nt * 8 + gg;
                int rk = kt * 8 + t4;
                bf[nt][0] = __float_as_uint(B_[rk * 136 + cb]);
                bf[nt][1] = __float_as_uint(B_[(rk + 4) * 136 + cb]);
            }
            #pragma unroll
            for (int mt = 0; mt < 4; mt++)
                #pragma unroll
                for (int nt = 0; nt < 4; nt++)
                    mma8(acc[mt][nt], af[mt], bf[nt]);
        }
    };

    // ---- main loop ----
    ldg(0);
    sts(0);
    __syncthreads();
    for (int c = 0; c < NC; c++) {
        if (c + 1 < NC) ldg((c + 1) * 32);
        comp(c & 1);
        if (c + 1 < NC) sts((c + 1) & 1);
        __syncthreads();
    }

    // ---- epilogue ----
    #pragma unroll
    for (int mt = 0; mt < 4; mt++) {
        int r_lo = wm * 64 + mt * 16 + gg;
        #pragma unroll
        for (int half = 0; half < 2; half++) {
            int r = r_lo + half * 8;
            float* drow = nullptr;
            if (!ROUTED) drow = Dbase + (size_t)(row0 + r) * LDB;
            else { int a = aidx[r]; if (a >= 0) drow = Dbase + (size_t)a * LDB; }
            if (drow) {
                #pragma unroll
                for (int nt = 0; nt < 4; nt++) {
                    int cc = col0 + wn * 32 + nt * 8 + t4 * 2;
                    float2 v = half == 0
                        ? make_float2(acc[mt][nt][0], acc[mt][nt][1])
                        : make_float2(acc[mt][nt][2], acc[mt][nt][3]);
                    *(float2*)(drow + cc) = v;
                }
            }
        }
    }
}

// ---------------- activation kernels ----------------
__global__ void act_routed_kernel() {
    const int C4 = II / 4;  // 352
    int idx = blockIdx.x * blockDim.x + threadIdx.x;
    if (idx >= NA * C4) return;
    int a = idx / C4;
    int c = (idx % C4) * 4;
    const float* row = g_gu + (size_t)a * (2 * II);
    float4 gv = *(const float4*)(row + c);
    float4 uv = *(const float4*)(row + II + c);
    float wt = g_topk_w[a];
    float4 o;
    o.x = gv.x / (1.f + expf(-gv.x)) * uv.x * wt;
    o.y = gv.y / (1.f + expf(-gv.y)) * uv.y * wt;
    o.z = gv.z / (1.f + expf(-gv.z)) * uv.z * wt;
    o.w = gv.w / (1.f + expf(-gv.w)) * uv.w * wt;
    *(float4*)(g_h + (size_t)a * II + c) = o;
}

__global__ void act_shared_kernel() {
    const int C4 = IS / 4;  // 704
    int idx = blockIdx.x * blockDim.x + threadIdx.x;
    if (idx >= T * C4) return;
    int t = idx / C4;
    int c = (idx % C4) * 4;
    const float* row = g_sgu + (size_t)t * (2 * IS);
    float4 gv = *(const float4*)(row + c);
    float4 uv = *(const float4*)(row + IS + c);
    float4 o;
    o.x = gv.x / (1.f + expf(-gv.x)) * uv.x;
    o.y = gv.y / (1.f + expf(-gv.y)) * uv.y;
    o.z = gv.z / (1.f + expf(-gv.z)) * uv.z;
    o.w = gv.w / (1.f + expf(-gv.w)) * uv.w;
    *(float4*)(g_shh + (size_t)t * IS + c) = o;
}

// ---------------- combine: out += SCALE * sum_k y ----------------
__global__ void combine_kernel(float* __restrict__ out) {
    int idx = blockIdx.x * blockDim.x + threadIdx.x;
    if (idx >= (T * H) / 4) return;
    int t = idx / (H / 4);
    int c4 = idx % (H / 4);
    float4 acc = make_float4(0.f, 0.f, 0.f, 0.f);
    #pragma unroll
    for (int k = 0; k < KSEL; k++) {
        const float4 v = *(const float4*)(g_y + (size_t)(t * KSEL + k) * H + c4 * 4);
        acc.x += v.x; acc.y += v.y; acc.z += v.z; acc.w += v.w;
    }
    float4* o = (float4*)(out + (size_t)t * H + c4 * 4);
    float4 cur = *o;
    cur.x += SCALEF * acc.x;
    cur.y += SCALEF * acc.y;
    cur.z += SCALEF * acc.z;
    cur.w += SCALEF * acc.w;
    *o = cur;
}

// ---------------- launch ----------------
extern "C" void kernel_launch(void* const* d_in, const int* in_sizes, int n_in,
                              void* d_out, int out_size) {
    const float* x   = (const float*)d_in[0];
    const float* gw  = (const float*)d_in[1];
    const float* gb  = (const float*)d_in[2];
    const float* w1  = (const float*)d_in[3];
    const float* w2  = (const float*)d_in[4];
    const float* sw1 = (const float*)d_in[5];
    const float* sw2 = (const float*)d_in[6];
    float* out = (float*)d_out;

    cudaFuncSetAttribute(gemm_tc<0>, cudaFuncAttributeMaxDynamicSharedMemorySize, SMEM_GEMM);
    cudaFuncSetAttribute(gemm_tc<1>, cudaFuncAttributeMaxDynamicSharedMemorySize, SMEM_GEMM);
    cudaFuncSetAttribute(gemm_tc<2>, cudaFuncAttributeMaxDynamicSharedMemorySize, SMEM_GEMM);
    cudaFuncSetAttribute(gemm_tc<3>, cudaFuncAttributeMaxDynamicSharedMemorySize, SMEM_GEMM);

    reset_kernel<<<1, 32>>>();
    router_kernel<<<T, 128>>>(x, gw, gb);
    scan_kernel<<<1, 32>>>();
    fill_kernel<<<(NA + 255) / 256, 256>>>();

    // shared expert
    gemm_tc<0><<<dim3(2 * IS / 128, T / 128, 1), 256, SMEM_GEMM>>>(x, sw1, nullptr);
    act_shared_kernel<<<(T * (IS / 4) + 255) / 256, 256>>>();
    gemm_tc<1><<<dim3(H / 128, T / 128, 1), 256, SMEM_GEMM>>>(nullptr, sw2, out);

    // routed experts (grouped; y sized for worst-case 2048 rows/expert)
    gemm_tc<2><<<dim3(2 * II / 128, 16, E), 256, SMEM_GEMM>>>(x, w1, nullptr);
    act_routed_kernel<<<(NA * (II / 4) + 255) / 256, 256>>>();
    gemm_tc<3><<<dim3(H / 128, 16, E), 256, SMEM_GEMM>>>(nullptr, w2, nullptr);

    combine_kernel<<<((T * H / 4) + 255) / 256, 256>>>(out);
}

// round 4
// speedup vs baseline: 4.4736x; 2.5596x over previous
#include <cuda_runtime.h>
#include <cuda_fp16.h>
#include <math.h>
#include <stdint.h>

#define T 2048
#define H 2048
#define E 32
#define KSEL 6
#define G 8
#define TOPKG 4
#define II 1408
#define IS 2816
#define SCALEF 2.5f
#define NA (T*KSEL)   // 12288 assignments

// ---------------- scratch (allocation-free: __device__ globals) ----------------
__device__ float g_topk_w[NA];
__device__ int   g_topk_id[NA];
__device__ int   g_cnt[E];
__device__ int   g_off[E];
__device__ int   g_cur[E];
__device__ int   g_alist[NA];
__device__ float g_gu[(size_t)NA * 2 * II];   // routed gate|up  ~138 MB
__device__ float g_h[(size_t)NA * II];        // routed hidden   ~69 MB
__device__ float g_y[(size_t)NA * H];         // routed out      ~101 MB
__device__ float g_sgu[(size_t)T * 2 * IS];   // shared gate|up  ~46 MB
__device__ float g_shh[(size_t)T * IS];       // shared hidden   ~23 MB

// ---------------- helpers ----------------
__device__ __forceinline__ uint32_t smem_u32(const void* p) {
    uint32_t a;
    asm("{ .reg .u64 t; cvta.to.shared.u64 t, %1; cvt.u32.u64 %0, t; }" : "=r"(a) : "l"(p));
    return a;
}
__device__ __forceinline__ uint32_t pk2(float a, float b) {
    __half2 h = __floats2half2_rn(a, b);
    return *(uint32_t*)&h;
}
__device__ __forceinline__ void ldmx4(uint32_t* r, uint32_t addr) {
    asm volatile("ldmatrix.sync.aligned.m8n8.x4.shared.b16 {%0,%1,%2,%3}, [%4];"
                 : "=r"(r[0]), "=r"(r[1]), "=r"(r[2]), "=r"(r[3]) : "r"(addr));
}
__device__ __forceinline__ void mma16(float* d, const uint32_t* a, uint32_t b0, uint32_t b1) {
    asm volatile(
        "mma.sync.aligned.m16n8k16.row.col.f32.f16.f16.f32 "
        "{%0,%1,%2,%3}, {%4,%5,%6,%7}, {%8,%9}, {%0,%1,%2,%3};"
        : "+f"(d[0]), "+f"(d[1]), "+f"(d[2]), "+f"(d[3])
        : "r"(a[0]), "r"(a[1]), "r"(a[2]), "r"(a[3]), "r"(b0), "r"(b1));
}

// ---------------- small kernels ----------------
__global__ void reset_kernel() {
    if (threadIdx.x < E) g_cnt[threadIdx.x] = 0;
}

__global__ void router_kernel(const float* __restrict__ x,
                              const float* __restrict__ gw,
                              const float* __restrict__ gb) {
    int t = blockIdx.x;
    __shared__ float xs[H];
    __shared__ float logit[E];
    for (int i = threadIdx.x; i < H; i += blockDim.x) xs[i] = x[(size_t)t * H + i];
    __syncthreads();
    int warp = threadIdx.x >> 5, lane = threadIdx.x & 31;
    for (int e = warp; e < E; e += 4) {
        const float* w = gw + (size_t)e * H;
        float s = 0.f;
        for (int i = lane; i < H; i += 32) s += xs[i] * w[i];
        #pragma unroll
        for (int o = 16; o; o >>= 1) s += __shfl_xor_sync(0xffffffffu, s, o);
        if (lane == 0) logit[e] = s;
    }
    __syncthreads();
    if (threadIdx.x == 0) {
        float sc[E], ss[E];
        #pragma unroll
        for (int e = 0; e < E; e++) {
            float s = 1.f / (1.f + expf(-logit[e]));
            ss[e] = s;
            sc[e] = s + gb[e];
        }
        float gsc[G];
        #pragma unroll
        for (int g = 0; g < G; g++) {
            float m1 = -1e30f, m2 = -1e30f;
            #pragma unroll
            for (int j = 0; j < 4; j++) {
                float v = sc[g * 4 + j];
                if (v > m1) { m2 = m1; m1 = v; } else if (v > m2) m2 = v;
            }
            gsc[g] = m1 + m2;
        }
        bool gsel[G];
        #pragma unroll
        for (int g = 0; g < G; g++) gsel[g] = false;
        for (int r = 0; r < TOPKG; r++) {
            int best = -1; float bv = -1e30f;
            for (int g = 0; g < G; g++)
                if (!gsel[g] && gsc[g] > bv) { bv = gsc[g]; best = g; }
            gsel[best] = true;
        }
        bool esel[E];
        #pragma unroll
        for (int e = 0; e < E; e++) esel[e] = false;
        int ids[KSEL];
        for (int r = 0; r < KSEL; r++) {
            int best = -1; float bv = -1e30f;
            for (int e = 0; e < E; e++) {
                if (esel[e] || !gsel[e >> 2]) continue;
                if (sc[e] > bv) { bv = sc[e]; best = e; }
            }
            esel[best] = true; ids[r] = best;
        }
        float w[KSEL], wsum = 0.f;
        for (int r = 0; r < KSEL; r++) { w[r] = ss[ids[r]]; wsum += w[r]; }
        float inv = 1.f / wsum;
        for (int r = 0; r < KSEL; r++) {
            g_topk_w[t * KSEL + r] = w[r] * inv;
            g_topk_id[t * KSEL + r] = ids[r];
            atomicAdd(&g_cnt[ids[r]], 1);
        }
    }
}

__global__ void scan_kernel() {
    if (threadIdx.x == 0) {
        int run = 0;
        for (int e = 0; e < E; e++) {
            g_off[e] = run;
            g_cur[e] = run;
            run += g_cnt[e];
        }
    }
}

__global__ void fill_kernel() {
    int a = blockIdx.x * blockDim.x + threadIdx.x;
    if (a >= NA) return;
    int e = g_topk_id[a];
    int pos = atomicAdd(&g_cur[e], 1);
    g_alist[pos] = a;
}

// ---------------- fp16 tensor-core GEMM (mma.sync m16n8k16 + ldmatrix) ----------------
// 128x128 block tile, K-chunk 64, 8 warps (2x4), warp tile 64x32.
// smem: A [128 rows][72 halves]=144B stride; B transposed [128 n][72 halves].
// MODE 0: shared gate_up : A = x[t] (K=H),      B = sw1 (N=2*IS), D = g_sgu
// MODE 1: shared down    : A = g_shh[t] (K=IS), B = sw2 (N=H),    D = out
// MODE 2: routed gate_up : A = x[a/K] (K=H),    B = w1[e] (N=2*II), D = g_gu (row a)
// MODE 3: routed down    : A = g_h[a] (K=II),   B = w2[e] (N=H),    D = g_y (row a)
#define ASTG 18432               // 128*144 bytes per stage
#define SMEM_GEMM (4*ASTG + 1536)

template<int MODE>
__global__ void __launch_bounds__(256, 1)
gemm_tc(const float* __restrict__ X, const float* __restrict__ W, float* __restrict__ Dout)
{
    constexpr bool ROUTED = (MODE >= 2);
    constexpr int KTOT = (MODE == 0) ? H : (MODE == 1) ? IS : (MODE == 2) ? H : II;
    constexpr int LDB  = (MODE == 0) ? 2 * IS : (MODE == 1) ? H : (MODE == 2) ? 2 * II : H;
    constexpr int NC   = KTOT / 64;

    extern __shared__ char smem[];
    const uint32_t sbase = smem_u32(smem);
    float* meta = (float*)(smem + 4 * ASTG);
    const float** rowptr = (const float**)meta;   // 128 ptrs
    int* aidx = (int*)(meta + 256);               // 128 ints

    int n, off = 0;
    const float* Bg = W;
    if (ROUTED) {
        int e = blockIdx.z;
        n = g_cnt[e]; off = g_off[e];
        if ((int)(blockIdx.y * 128) >= n) return;
        Bg = W + (size_t)e * (size_t)KTOT * LDB;
    } else n = T;

    const int row0 = blockIdx.y * 128;
    const int col0 = blockIdx.x * 128;
    const int tid = threadIdx.x;

    if (tid < 128) {
        int gr = row0 + tid;
        int a = -1;
        const float* p;
        if (MODE == 0)      p = X + (size_t)gr * H;
        else if (MODE == 1) p = g_shh + (size_t)gr * IS;
        else {
            if (gr < n) a = g_alist[off + gr];
            int aa = (a >= 0) ? a : g_alist[off];
            if (MODE == 2) p = X + (size_t)(aa / KSEL) * H;
            else           p = g_h + (size_t)aa * II;
        }
        rowptr[tid] = p;
        aidx[tid] = a;
    }
    __syncthreads();

    float* Dbase = (MODE == 1) ? Dout : (MODE == 0 ? g_sgu : (MODE == 2 ? g_gu : g_y));

    const int lane = tid & 31, wid = tid >> 5;
    const int wm = wid >> 2, wn = wid & 3;
    const int gg = lane >> 2, t4 = lane & 3;

    float4 aR[8];
    float  bR[8][4];
    float  acc[4][4][4] = {};

    auto ldg = [&](int k0) {
        #pragma unroll
        for (int r = 0; r < 4; r++) {
            int u = tid + 256 * r;
            int m = u >> 3, kb = (u & 7) * 8;
            const float* rp = rowptr[m] + k0 + kb;
            aR[2 * r]     = *(const float4*)(rp);
            aR[2 * r + 1] = *(const float4*)(rp + 4);
        }
        #pragma unroll
        for (int r = 0; r < 8; r++) {
            int u = tid + 256 * r;
            int nn = u & 127, kg = u >> 7;
            const float* gp = Bg + (size_t)(k0 + kg * 4) * LDB + col0 + nn;
            #pragma unroll
            for (int j = 0; j < 4; j++) bR[r][j] = gp[(size_t)j * LDB];
        }
    };
    auto sts = [&](int s) {
        char* A_ = smem + s * ASTG;
        char* B_ = smem + (2 + s) * ASTG;
        #pragma unroll
        for (int r = 0; r < 4; r++) {
            int u = tid + 256 * r;
            int m = u >> 3, kb = (u & 7) * 8;
            uint4 v = make_uint4(pk2(aR[2*r].x, aR[2*r].y), pk2(aR[2*r].z, aR[2*r].w),
                                 pk2(aR[2*r+1].x, aR[2*r+1].y), pk2(aR[2*r+1].z, aR[2*r+1].w));
            *(uint4*)(A_ + m * 144 + kb * 2) = v;
        }
        #pragma unroll
        for (int r = 0; r < 8; r++) {
            int u = tid + 256 * r;
            int nn = u & 127, kg = u >> 7;
            uint2 v = make_uint2(pk2(bR[r][0], bR[r][1]), pk2(bR[r][2], bR[r][3]));
            *(uint2*)(B_ + nn * 144 + kg * 8) = v;
        }
    };
    auto comp = [&](int s) {
        const uint32_t Ab = sbase + s * ASTG;
        const uint32_t Bb = sbase + (2 + s) * ASTG;
        const int lrA = (lane & 7) + ((lane >> 3) & 1) * 8;   // row within 16
        const int lkA = (lane >> 4) * 8;                      // 0 or 8 halves
        const int lrB = (lane & 7) + (lane >> 4) * 8;
        const int lkB = ((lane >> 3) & 1) * 8;
        #pragma unroll
        for (int ks = 0; ks < 4; ks++) {
            const int kh = ks * 16;
            uint32_t af[4][4];
            #pragma unroll
            for (int mt = 0; mt < 4; mt++)
                ldmx4(af[mt], Ab + (wm * 64 + mt * 16 + lrA) * 144 + (kh + lkA) * 2);
            uint32_t bf[2][4];
            #pragma unroll
            for (int np = 0; np < 2; np++)
                ldmx4(bf[np], Bb + (wn * 32 + np * 16 + lrB) * 144 + (kh + lkB) * 2);
            #pragma unroll
            for (int mt = 0; mt < 4; mt++)
                #pragma unroll
                for (int nt = 0; nt < 4; nt++)
                    mma16(acc[mt][nt], af[mt], bf[nt >> 1][(nt & 1) * 2], bf[nt >> 1][(nt & 1) * 2 + 1]);
        }
    };

    ldg(0);
    sts(0);
    __syncthreads();
    for (int c = 0; c < NC; c++) {
        if (c + 1 < NC) ldg((c + 1) * 64);
        comp(c & 1);
        if (c + 1 < NC) sts((c + 1) & 1);
        __syncthreads();
    }

    // ---- epilogue ----
    #pragma unroll
    for (int mt = 0; mt < 4; mt++) {
        int r_lo = wm * 64 + mt * 16 + gg;
        #pragma unroll
        for (int half = 0; half < 2; half++) {
            int r = r_lo + half * 8;
            float* drow = nullptr;
            if (!ROUTED) drow = Dbase + (size_t)(row0 + r) * LDB;
            else { int a = aidx[r]; if (a >= 0) drow = Dbase + (size_t)a * LDB; }
            if (drow) {
                #pragma unroll
                for (int nt = 0; nt < 4; nt++) {
                    int cc = col0 + wn * 32 + nt * 8 + t4 * 2;
                    float2 v = half == 0
                        ? make_float2(acc[mt][nt][0], acc[mt][nt][1])
                        : make_float2(acc[mt][nt][2], acc[mt][nt][3]);
                    *(float2*)(drow + cc) = v;
                }
            }
        }
    }
}

// ---------------- activation kernels ----------------
__global__ void act_routed_kernel() {
    const int C4 = II / 4;  // 352
    int idx = blockIdx.x * blockDim.x + threadIdx.x;
    if (idx >= NA * C4) return;
    int a = idx / C4;
    int c = (idx % C4) * 4;
    const float* row = g_gu + (size_t)a * (2 * II);
    float4 gv = *(const float4*)(row + c);
    float4 uv = *(const float4*)(row + II + c);
    float wt = g_topk_w[a];
    float4 o;
    o.x = gv.x / (1.f + expf(-gv.x)) * uv.x * wt;
    o.y = gv.y / (1.f + expf(-gv.y)) * uv.y * wt;
    o.z = gv.z / (1.f + expf(-gv.z)) * uv.z * wt;
    o.w = gv.w / (1.f + expf(-gv.w)) * uv.w * wt;
    *(float4*)(g_h + (size_t)a * II + c) = o;
}

__global__ void act_shared_kernel() {
    const int C4 = IS / 4;  // 704
    int idx = blockIdx.x * blockDim.x + threadIdx.x;
    if (idx >= T * C4) return;
    int t = idx / C4;
    int c = (idx % C4) * 4;
    const float* row = g_sgu + (size_t)t * (2 * IS);
    float4 gv = *(const float4*)(row + c);
    float4 uv = *(const float4*)(row + IS + c);
    float4 o;
    o.x = gv.x / (1.f + expf(-gv.x)) * uv.x;
    o.y = gv.y / (1.f + expf(-gv.y)) * uv.y;
    o.z = gv.z / (1.f + expf(-gv.z)) * uv.z;
    o.w = gv.w / (1.f + expf(-gv.w)) * uv.w;
    *(float4*)(g_shh + (size_t)t * IS + c) = o;
}

// ---------------- combine: out += SCALE * sum_k y ----------------
__global__ void combine_kernel(float* __restrict__ out) {
    int idx = blockIdx.x * blockDim.x + threadIdx.x;
    if (idx >= (T * H) / 4) return;
    int t = idx / (H / 4);
    int c4 = idx % (H / 4);
    float4 acc = make_float4(0.f, 0.f, 0.f, 0.f);
    #pragma unroll
    for (int k = 0; k < KSEL; k++) {
        const float4 v = *(const float4*)(g_y + (size_t)(t * KSEL + k) * H + c4 * 4);
        acc.x += v.x; acc.y += v.y; acc.z += v.z; acc.w += v.w;
    }
    float4* o = (float4*)(out + (size_t)t * H + c4 * 4);
    float4 cur = *o;
    cur.x += SCALEF * acc.x;
    cur.y += SCALEF * acc.y;
    cur.z += SCALEF * acc.z;
    cur.w += SCALEF * acc.w;
    *o = cur;
}

// ---------------- launch ----------------
extern "C" void kernel_launch(void* const* d_in, const int* in_sizes, int n_in,
                              void* d_out, int out_size) {
    const float* x   = (const float*)d_in[0];
    const float* gw  = (const float*)d_in[1];
    const float* gb  = (const float*)d_in[2];
    const float* w1  = (const float*)d_in[3];
    const float* w2  = (const float*)d_in[4];
    const float* sw1 = (const float*)d_in[5];
    const float* sw2 = (const float*)d_in[6];
    float* out = (float*)d_out;

    cudaFuncSetAttribute(gemm_tc<0>, cudaFuncAttributeMaxDynamicSharedMemorySize, SMEM_GEMM);
    cudaFuncSetAttribute(gemm_tc<1>, cudaFuncAttributeMaxDynamicSharedMemorySize, SMEM_GEMM);
    cudaFuncSetAttribute(gemm_tc<2>, cudaFuncAttributeMaxDynamicSharedMemorySize, SMEM_GEMM);
    cudaFuncSetAttribute(gemm_tc<3>, cudaFuncAttributeMaxDynamicSharedMemorySize, SMEM_GEMM);

    reset_kernel<<<1, 32>>>();
    router_kernel<<<T, 128>>>(x, gw, gb);
    scan_kernel<<<1, 32>>>();
    fill_kernel<<<(NA + 255) / 256, 256>>>();

    // shared expert
    gemm_tc<0><<<dim3(2 * IS / 128, T / 128, 1), 256, SMEM_GEMM>>>(x, sw1, nullptr);
    act_shared_kernel<<<(T * (IS / 4) + 255) / 256, 256>>>();
    gemm_tc<1><<<dim3(H / 128, T / 128, 1), 256, SMEM_GEMM>>>(nullptr, sw2, out);

    // routed experts (grouped)
    gemm_tc<2><<<dim3(2 * II / 128, 16, E), 256, SMEM_GEMM>>>(x, w1, nullptr);
    act_routed_kernel<<<(NA * (II / 4) + 255) / 256, 256>>>();
    gemm_tc<3><<<dim3(H / 128, 16, E), 256, SMEM_GEMM>>>(nullptr, w2, nullptr);

    combine_kernel<<<((T * H / 4) + 255) / 256, 256>>>(out);
}

// round 5
// speedup vs baseline: 5.0429x; 1.1273x over previous
#include <cuda_runtime.h>
#include <cuda_fp16.h>
#include <math.h>
#include <stdint.h>

#define T 2048
#define H 2048
#define E 32
#define KSEL 6
#define G 8
#define TOPKG 4
#define II 1408
#define IS 2816
#define SCALEF 2.5f
#define NA (T*KSEL)   // 12288 assignments

// ---------------- scratch (allocation-free: __device__ globals) ----------------
__device__ float  g_topk_w[NA];
__device__ int    g_topk_id[NA];
__device__ int    g_cnt[E];
__device__ int    g_off[E];
__device__ int    g_cur[E];
__device__ int    g_alist[NA];
__device__ __half g_xh[(size_t)T * H];        // x in fp16 (8 MB)
__device__ __half g_hh[(size_t)NA * II];      // routed hidden fp16 (~35 MB)
__device__ __half g_shh[(size_t)T * IS];      // shared hidden fp16 (~12 MB)
__device__ float  g_y[(size_t)NA * H];        // routed out (~101 MB)

// ---------------- helpers ----------------
__device__ __forceinline__ uint32_t smem_u32(const void* p) {
    uint32_t a;
    asm("{ .reg .u64 t; cvta.to.shared.u64 t, %1; cvt.u32.u64 %0, t; }" : "=r"(a) : "l"(p));
    return a;
}
__device__ __forceinline__ uint32_t pk2(float a, float b) {
    __half2 h = __floats2half2_rn(a, b);
    return *(uint32_t*)&h;
}
__device__ __forceinline__ void cpasync16(uint32_t dst, const void* src) {
    asm volatile("cp.async.cg.shared.global [%0], [%1], 16;" :: "r"(dst), "l"(src));
}
__device__ __forceinline__ void cp_commit() {
    asm volatile("cp.async.commit_group;" ::: "memory");
}
__device__ __forceinline__ void cp_wait0() {
    asm volatile("cp.async.wait_group 0;" ::: "memory");
}
__device__ __forceinline__ void ldmx4(uint32_t* r, uint32_t addr) {
    asm volatile("ldmatrix.sync.aligned.m8n8.x4.shared.b16 {%0,%1,%2,%3}, [%4];"
                 : "=r"(r[0]), "=r"(r[1]), "=r"(r[2]), "=r"(r[3]) : "r"(addr));
}
__device__ __forceinline__ void mma16(float* d, const uint32_t* a, uint32_t b0, uint32_t b1) {
    asm volatile(
        "mma.sync.aligned.m16n8k16.row.col.f32.f16.f16.f32 "
        "{%0,%1,%2,%3}, {%4,%5,%6,%7}, {%8,%9}, {%0,%1,%2,%3};"
        : "+f"(d[0]), "+f"(d[1]), "+f"(d[2]), "+f"(d[3])
        : "r"(a[0]), "r"(a[1]), "r"(a[2]), "r"(a[3]), "r"(b0), "r"(b1));
}
__device__ __forceinline__ float silu(float g) { return g / (1.f + expf(-g)); }

// ---------------- small kernels ----------------
__global__ void reset_kernel() {
    if (threadIdx.x < E) g_cnt[threadIdx.x] = 0;
}

__global__ void xhalf_kernel(const float* __restrict__ x) {
    int idx = blockIdx.x * blockDim.x + threadIdx.x;
    if (idx >= (T * H) / 4) return;
    float4 v = *(const float4*)(x + (size_t)idx * 4);
    uint2 o = make_uint2(pk2(v.x, v.y), pk2(v.z, v.w));
    *(uint2*)(g_xh + (size_t)idx * 4) = o;
}

__global__ void router_kernel(const float* __restrict__ x,
                              const float* __restrict__ gw,
                              const float* __restrict__ gb) {
    int t = blockIdx.x;
    __shared__ float xs[H];
    __shared__ float logit[E];
    for (int i = threadIdx.x; i < H; i += blockDim.x) xs[i] = x[(size_t)t * H + i];
    __syncthreads();
    int warp = threadIdx.x >> 5, lane = threadIdx.x & 31;
    for (int e = warp; e < E; e += 4) {
        const float* w = gw + (size_t)e * H;
        float s = 0.f;
        for (int i = lane; i < H; i += 32) s += xs[i] * w[i];
        #pragma unroll
        for (int o = 16; o; o >>= 1) s += __shfl_xor_sync(0xffffffffu, s, o);
        if (lane == 0) logit[e] = s;
    }
    __syncthreads();
    if (threadIdx.x == 0) {
        float sc[E], ss[E];
        #pragma unroll
        for (int e = 0; e < E; e++) {
            float s = 1.f / (1.f + expf(-logit[e]));
            ss[e] = s;
            sc[e] = s + gb[e];
        }
        float gsc[G];
        #pragma unroll
        for (int g = 0; g < G; g++) {
            float m1 = -1e30f, m2 = -1e30f;
            #pragma unroll
            for (int j = 0; j < 4; j++) {
                float v = sc[g * 4 + j];
                if (v > m1) { m2 = m1; m1 = v; } else if (v > m2) m2 = v;
            }
            gsc[g] = m1 + m2;
        }
        bool gsel[G];
        #pragma unroll
        for (int g = 0; g < G; g++) gsel[g] = false;
        for (int r = 0; r < TOPKG; r++) {
            int best = -1; float bv = -1e30f;
            for (int g = 0; g < G; g++)
                if (!gsel[g] && gsc[g] > bv) { bv = gsc[g]; best = g; }
            gsel[best] = true;
        }
        bool esel[E];
        #pragma unroll
        for (int e = 0; e < E; e++) esel[e] = false;
        int ids[KSEL];
        for (int r = 0; r < KSEL; r++) {
            int best = -1; float bv = -1e30f;
            for (int e = 0; e < E; e++) {
                if (esel[e] || !gsel[e >> 2]) continue;
                if (sc[e] > bv) { bv = sc[e]; best = e; }
            }
            esel[best] = true; ids[r] = best;
        }
        float w[KSEL], wsum = 0.f;
        for (int r = 0; r < KSEL; r++) { w[r] = ss[ids[r]]; wsum += w[r]; }
        float inv = 1.f / wsum;
        for (int r = 0; r < KSEL; r++) {
            g_topk_w[t * KSEL + r] = w[r] * inv;
            g_topk_id[t * KSEL + r] = ids[r];
            atomicAdd(&g_cnt[ids[r]], 1);
        }
    }
}

__global__ void scan_kernel() {
    if (threadIdx.x == 0) {
        int run = 0;
        for (int e = 0; e < E; e++) {
            g_off[e] = run;
            g_cur[e] = run;
            run += g_cnt[e];
        }
    }
}

__global__ void fill_kernel() {
    int a = blockIdx.x * blockDim.x + threadIdx.x;
    if (a >= NA) return;
    int e = g_topk_id[a];
    int pos = atomicAdd(&g_cur[e], 1);
    g_alist[pos] = a;
}

// =====================================================================
// Fused gate_up GEMM + silu*mul(*wt) -> fp16 hidden.
// Block 128 rows x 128 hidden cols; K-chunk 32; 8 warps (2x4), warp 64x32.
// A fp16 via cp.async (row stride 80B, conflict-free for ldmatrix).
// Two B tiles (gate & up) fp32->fp16 via registers.
// =====================================================================
#define ASTG_F 10240     // 128 * 80
#define SMEM_F (6*ASTG_F + 2048)

template<bool ROUTED>
__global__ void __launch_bounds__(256, 1)
gemm_gateup(const float* __restrict__ W)
{
    constexpr int NPER = ROUTED ? II : IS;
    constexpr int LDB  = 2 * NPER;
    constexpr int NC   = H / 32;

    extern __shared__ char smem[];
    const uint32_t sbase = smem_u32(smem);
    char* meta = smem + 6 * ASTG_F;
    const __half** rowptr = (const __half**)meta;     // 128 ptrs
    int* aidx = (int*)(meta + 1024);                  // 128 ints

    int n, off = 0;
    const float* Bb = W;
    if (ROUTED) {
        int e = blockIdx.z;
        n = g_cnt[e]; off = g_off[e];
        if ((int)(blockIdx.y * 128) >= n) return;
        Bb = W + (size_t)e * (size_t)H * LDB;
    } else n = T;

    const int row0 = blockIdx.y * 128;
    const int col0 = blockIdx.x * 128;
    const int tid = threadIdx.x;

    if (tid < 128) {
        int gr = row0 + tid;
        int a = -1;
        if (ROUTED && gr < n) a = g_alist[off + gr];
        int aa = (!ROUTED) ? gr : ((a >= 0 ? a : g_alist[off]) / KSEL);
        rowptr[tid] = g_xh + (size_t)aa * H;
        aidx[tid] = a;
    }
    __syncthreads();

    const int lane = tid & 31, wid = tid >> 5;
    const int wm = wid >> 2, wn = wid & 3;
    const int gg = lane >> 2, t4 = lane & 3;

    float bRg[4][4], bRu[4][4];
    float accg[4][4][4] = {}, accu[4][4][4] = {};

    auto cpA = [&](int k0, int s) {
        #pragma unroll
        for (int r = 0; r < 2; r++) {
            int u = tid + 256 * r;
            int m = u >> 2, kq = u & 3;
            cpasync16(sbase + s * ASTG_F + m * 80 + kq * 16, rowptr[m] + k0 + kq * 8);
        }
    };
    auto ldgB = [&](int k0) {
        #pragma unroll
        for (int r = 0; r < 4; r++) {
            int u = tid + 256 * r;
            int nn = u & 127, kg = u >> 7;   // kg 0..7 (k-groups of 4)
            const float* gp = Bb + (size_t)(k0 + kg * 4) * LDB + col0 + nn;
            #pragma unroll
            for (int j = 0; j < 4; j++) {
                bRg[r][j] = gp[(size_t)j * LDB];
                bRu[r][j] = gp[(size_t)j * LDB + NPER];
            }
        }
    };
    auto stsB = [&](int s) {
        char* Bg_ = smem + (2 + s) * ASTG_F;
        char* Bu_ = smem + (4 + s) * ASTG_F;
        #pragma unroll
        for (int r = 0; r < 4; r++) {
            int u = tid + 256 * r;
            int nn = u & 127, kg = u >> 7;
            *(uint2*)(Bg_ + nn * 80 + kg * 8) = make_uint2(pk2(bRg[r][0], bRg[r][1]), pk2(bRg[r][2], bRg[r][3]));
            *(uint2*)(Bu_ + nn * 80 + kg * 8) = make_uint2(pk2(bRu[r][0], bRu[r][1]), pk2(bRu[r][2], bRu[r][3]));
        }
    };
    const int lrA = (lane & 7) + ((lane >> 3) & 1) * 8;
    const int lkA = (lane >> 4) * 8;
    const int lrB = (lane & 7) + (lane >> 4) * 8;
    const int lkB = ((lane >> 3) & 1) * 8;
    auto comp = [&](int s) {
        const uint32_t Ab = sbase + s * ASTG_F;
        const uint32_t Bgb = sbase + (2 + s) * ASTG_F;
        const uint32_t Bub = sbase + (4 + s) * ASTG_F;
        #pragma unroll
        for (int ks = 0; ks < 2; ks++) {
            const int kh = ks * 16;
            uint32_t af[4][4];
            #pragma unroll
            for (int mt = 0; mt < 4; mt++)
                ldmx4(af[mt], Ab + (wm * 64 + mt * 16 + lrA) * 80 + (kh + lkA) * 2);
            uint32_t bfg[2][4], bfu[2][4];
            #pragma unroll
            for (int np = 0; np < 2; np++) {
                ldmx4(bfg[np], Bgb + (wn * 32 + np * 16 + lrB) * 80 + (kh + lkB) * 2);
                ldmx4(bfu[np], Bub + (wn * 32 + np * 16 + lrB) * 80 + (kh + lkB) * 2);
            }
            #pragma unroll
            for (int mt = 0; mt < 4; mt++)
                #pragma unroll
                for (int nt = 0; nt < 4; nt++) {
                    mma16(accg[mt][nt], af[mt], bfg[nt >> 1][(nt & 1) * 2], bfg[nt >> 1][(nt & 1) * 2 + 1]);
                    mma16(accu[mt][nt], af[mt], bfu[nt >> 1][(nt & 1) * 2], bfu[nt >> 1][(nt & 1) * 2 + 1]);
                }
        }
    };

    cpA(0, 0); cp_commit();
    ldgB(0);
    stsB(0);
    cp_wait0();
    __syncthreads();
    for (int c = 0; c < NC; c++) {
        if (c + 1 < NC) {
            cpA((c + 1) * 32, (c + 1) & 1); cp_commit();
            ldgB((c + 1) * 32);
        }
        comp(c & 1);
        if (c + 1 < NC) stsB((c + 1) & 1);
        cp_wait0();
        __syncthreads();
    }

    // epilogue: h = silu(g)*u*wt  -> fp16
    #pragma unroll
    for (int mt = 0; mt < 4; mt++) {
        #pragma unroll
        for (int hf = 0; hf < 2; hf++) {
            int r = wm * 64 + mt * 16 + gg + hf * 8;
            __half* drow = nullptr;
            float wt = 1.f;
            if (!ROUTED) drow = g_shh + (size_t)(row0 + r) * IS + col0;
            else {
                int a = aidx[r];
                if (a >= 0) { drow = g_hh + (size_t)a * II + col0; wt = g_topk_w[a]; }
            }
            if (drow) {
                #pragma unroll
                for (int nt = 0; nt < 4; nt++) {
                    int cc = wn * 32 + nt * 8 + t4 * 2;
                    float g0 = accg[mt][nt][hf * 2],     u0 = accu[mt][nt][hf * 2];
                    float g1 = accg[mt][nt][hf * 2 + 1], u1 = accu[mt][nt][hf * 2 + 1];
                    *(__half2*)(drow + cc) = __floats2half2_rn(silu(g0) * u0 * wt, silu(g1) * u1 * wt);
                }
            }
        }
    }
}

// =====================================================================
// Down-proj GEMM: A fp16 (cp.async), B fp32 w2/sw2 -> fp32 out.
// Block 128x128, K-chunk 64, 8 warps (2x4), warp 64x32. Row stride 144B.
// =====================================================================
#define ASTG_D 18432     // 128 * 144
#define SMEM_D (4*ASTG_D + 2048)

template<bool ROUTED>
__global__ void __launch_bounds__(256, 1)
gemm_down(const float* __restrict__ W, float* __restrict__ Dout)
{
    constexpr int KTOT = ROUTED ? II : IS;
    constexpr int NC   = KTOT / 64;

    extern __shared__ char smem[];
    const uint32_t sbase = smem_u32(smem);
    char* meta = smem + 4 * ASTG_D;
    const __half** rowptr = (const __half**)meta;
    int* aidx = (int*)(meta + 1024);

    int n, off = 0;
    const float* Bb = W;
    if (ROUTED) {
        int e = blockIdx.z;
        n = g_cnt[e]; off = g_off[e];
        if ((int)(blockIdx.y * 128) >= n) return;
        Bb = W + (size_t)e * (size_t)II * H;
    } else n = T;

    const int row0 = blockIdx.y * 128;
    const int col0 = blockIdx.x * 128;
    const int tid = threadIdx.x;

    if (tid < 128) {
        int gr = row0 + tid;
        int a = -1;
        const __half* p;
        if (!ROUTED) p = g_shh + (size_t)gr * IS;
        else {
            if (gr < n) a = g_alist[off + gr];
            int aa = a >= 0 ? a : g_alist[off];
            p = g_hh + (size_t)aa * II;
        }
        rowptr[tid] = p;
        aidx[tid] = a;
    }
    __syncthreads();

    const int lane = tid & 31, wid = tid >> 5;
    const int wm = wid >> 2, wn = wid & 3;
    const int gg = lane >> 2, t4 = lane & 3;

    float bR[8][4];
    float acc[4][4][4] = {};

    auto cpA = [&](int k0, int s) {
        #pragma unroll
        for (int r = 0; r < 4; r++) {
            int u = tid + 256 * r;
            int m = u >> 3, kq = u & 7;
            cpasync16(sbase + s * ASTG_D + m * 144 + kq * 16, rowptr[m] + k0 + kq * 8);
        }
    };
    auto ldgB = [&](int k0) {
        #pragma unroll
        for (int r = 0; r < 8; r++) {
            int u = tid + 256 * r;
            int nn = u & 127, kg = u >> 7;   // 0..15
            const float* gp = Bb + (size_t)(k0 + kg * 4) * H + col0 + nn;
            #pragma unroll
            for (int j = 0; j < 4; j++) bR[r][j] = gp[(size_t)j * H];
        }
    };
    auto stsB = [&](int s) {
        char* B_ = smem + (2 + s) * ASTG_D;
        #pragma unroll
        for (int r = 0; r < 8; r++) {
            int u = tid + 256 * r;
            int nn = u & 127, kg = u >> 7;
            *(uint2*)(B_ + nn * 144 + kg * 8) = make_uint2(pk2(bR[r][0], bR[r][1]), pk2(bR[r][2], bR[r][3]));
        }
    };
    const int lrA = (lane & 7) + ((lane >> 3) & 1) * 8;
    const int lkA = (lane >> 4) * 8;
    const int lrB = (lane & 7) + (lane >> 4) * 8;
    const int lkB = ((lane >> 3) & 1) * 8;
    auto comp = [&](int s) {
        const uint32_t Ab = sbase + s * ASTG_D;
        const uint32_t Bbs = sbase + (2 + s) * ASTG_D;
        #pragma unroll
        for (int ks = 0; ks < 4; ks++) {
            const int kh = ks * 16;
            uint32_t af[4][4];
            #pragma unroll
            for (int mt = 0; mt < 4; mt++)
                ldmx4(af[mt], Ab + (wm * 64 + mt * 16 + lrA) * 144 + (kh + lkA) * 2);
            uint32_t bf[2][4];
            #pragma unroll
            for (int np = 0; np < 2; np++)
                ldmx4(bf[np], Bbs + (wn * 32 + np * 16 + lrB) * 144 + (kh + lkB) * 2);
            #pragma unroll
            for (int mt = 0; mt < 4; mt++)
                #pragma unroll
                for (int nt = 0; nt < 4; nt++)
                    mma16(acc[mt][nt], af[mt], bf[nt >> 1][(nt & 1) * 2], bf[nt >> 1][(nt & 1) * 2 + 1]);
        }
    };

    cpA(0, 0); cp_commit();
    ldgB(0);
    stsB(0);
    cp_wait0();
    __syncthreads();
    for (int c = 0; c < NC; c++) {
        if (c + 1 < NC) {
            cpA((c + 1) * 64, (c + 1) & 1); cp_commit();
            ldgB((c + 1) * 64);
        }
        comp(c & 1);
        if (c + 1 < NC) stsB((c + 1) & 1);
        cp_wait0();
        __syncthreads();
    }

    #pragma unroll
    for (int mt = 0; mt < 4; mt++) {
        #pragma unroll
        for (int hf = 0; hf < 2; hf++) {
            int r = wm * 64 + mt * 16 + gg + hf * 8;
            float* drow = nullptr;
            if (!ROUTED) drow = Dout + (size_t)(row0 + r) * H + col0;
            else { int a = aidx[r]; if (a >= 0) drow = g_y + (size_t)a * H + col0; }
            if (drow) {
                #pragma unroll
                for (int nt = 0; nt < 4; nt++) {
                    int cc = wn * 32 + nt * 8 + t4 * 2;
                    *(float2*)(drow + cc) =
                        make_float2(acc[mt][nt][hf * 2], acc[mt][nt][hf * 2 + 1]);
                }
            }
        }
    }
}

// ---------------- combine: out += SCALE * sum_k y ----------------
__global__ void combine_kernel(float* __restrict__ out) {
    int idx = blockIdx.x * blockDim.x + threadIdx.x;
    if (idx >= (T * H) / 4) return;
    int t = idx / (H / 4);
    int c4 = idx % (H / 4);
    float4 acc = make_float4(0.f, 0.f, 0.f, 0.f);
    #pragma unroll
    for (int k = 0; k < KSEL; k++) {
        const float4 v = *(const float4*)(g_y + (size_t)(t * KSEL + k) * H + c4 * 4);
        acc.x += v.x; acc.y += v.y; acc.z += v.z; acc.w += v.w;
    }
    float4* o = (float4*)(out + (size_t)t * H + c4 * 4);
    float4 cur = *o;
    cur.x += SCALEF * acc.x;
    cur.y += SCALEF * acc.y;
    cur.z += SCALEF * acc.z;
    cur.w += SCALEF * acc.w;
    *o = cur;
}

// ---------------- launch ----------------
extern "C" void kernel_launch(void* const* d_in, const int* in_sizes, int n_in,
                              void* d_out, int out_size) {
    const float* x   = (const float*)d_in[0];
    const float* gw  = (const float*)d_in[1];
    const float* gb  = (const float*)d_in[2];
    const float* w1  = (const float*)d_in[3];
    const float* w2  = (const float*)d_in[4];
    const float* sw1 = (const float*)d_in[5];
    const float* sw2 = (const float*)d_in[6];
    float* out = (float*)d_out;

    cudaFuncSetAttribute(gemm_gateup<true>,  cudaFuncAttributeMaxDynamicSharedMemorySize, SMEM_F);
    cudaFuncSetAttribute(gemm_gateup<false>, cudaFuncAttributeMaxDynamicSharedMemorySize, SMEM_F);
    cudaFuncSetAttribute(gemm_down<true>,    cudaFuncAttributeMaxDynamicSharedMemorySize, SMEM_D);
    cudaFuncSetAttribute(gemm_down<false>,   cudaFuncAttributeMaxDynamicSharedMemorySize, SMEM_D);

    reset_kernel<<<1, 32>>>();
    xhalf_kernel<<<((T * H / 4) + 255) / 256, 256>>>(x);
    router_kernel<<<T, 128>>>(x, gw, gb);
    scan_kernel<<<1, 32>>>();
    fill_kernel<<<(NA + 255) / 256, 256>>>();

    // shared expert
    gemm_gateup<false><<<dim3(IS / 128, T / 128, 1), 256, SMEM_F>>>(sw1);
    gemm_down<false><<<dim3(H / 128, T / 128, 1), 256, SMEM_D>>>(sw2, out);

    // routed experts
    gemm_gateup<true><<<dim3(II / 128, 16, E), 256, SMEM_F>>>(w1);
    gemm_down<true><<<dim3(H / 128, 16, E), 256, SMEM_D>>>(w2, nullptr);

    combine_kernel<<<((T * H / 4) + 255) / 256, 256>>>(out);
}

// round 6
// speedup vs baseline: 5.0961x; 1.0105x over previous
#include <cuda_runtime.h>
#include <cuda_fp16.h>
#include <math.h>
#include <stdint.h>

#define T 2048
#define H 2048
#define E 32
#define KSEL 6
#define G 8
#define TOPKG 4
#define II 1408
#define IS 2816
#define SCALEF 2.5f
#define NA (T*KSEL)   // 12288 assignments

// ---------------- scratch (allocation-free: __device__ globals) ----------------
__device__ float  g_topk_w[NA];
__device__ int    g_topk_id[NA];
__device__ int    g_cnt[E];
__device__ int    g_off[E];
__device__ int    g_cur[E];
__device__ int    g_alist[NA];
__device__ __half g_xh[(size_t)T * H];        // x in fp16 (8 MB)
__device__ __half g_hh[(size_t)NA * II];      // routed hidden fp16 (~35 MB)
__device__ __half g_shh[(size_t)T * IS];      // shared hidden fp16 (~12 MB)
__device__ float  g_y[(size_t)NA * H];        // routed out (~101 MB)

// ---------------- helpers ----------------
__device__ __forceinline__ uint32_t smem_u32(const void* p) {
    uint32_t a;
    asm("{ .reg .u64 t; cvta.to.shared.u64 t, %1; cvt.u32.u64 %0, t; }" : "=r"(a) : "l"(p));
    return a;
}
__device__ __forceinline__ uint32_t pk2(float a, float b) {
    __half2 h = __floats2half2_rn(a, b);
    return *(uint32_t*)&h;
}
__device__ __forceinline__ void cpasync16(uint32_t dst, const void* src) {
    asm volatile("cp.async.cg.shared.global [%0], [%1], 16;" :: "r"(dst), "l"(src));
}
__device__ __forceinline__ void cp_commit() {
    asm volatile("cp.async.commit_group;" ::: "memory");
}
__device__ __forceinline__ void cp_wait0() {
    asm volatile("cp.async.wait_group 0;" ::: "memory");
}
__device__ __forceinline__ void ldmx4(uint32_t* r, uint32_t addr) {
    asm volatile("ldmatrix.sync.aligned.m8n8.x4.shared.b16 {%0,%1,%2,%3}, [%4];"
                 : "=r"(r[0]), "=r"(r[1]), "=r"(r[2]), "=r"(r[3]) : "r"(addr));
}
__device__ __forceinline__ void mma16(float* d, const uint32_t* a, uint32_t b0, uint32_t b1) {
    asm volatile(
        "mma.sync.aligned.m16n8k16.row.col.f32.f16.f16.f32 "
        "{%0,%1,%2,%3}, {%4,%5,%6,%7}, {%8,%9}, {%0,%1,%2,%3};"
        : "+f"(d[0]), "+f"(d[1]), "+f"(d[2]), "+f"(d[3])
        : "r"(a[0]), "r"(a[1]), "r"(a[2]), "r"(a[3]), "r"(b0), "r"(b1));
}
__device__ __forceinline__ float silu(float g) { return g / (1.f + expf(-g)); }

// ---------------- small kernels ----------------
__global__ void reset_kernel() {
    if (threadIdx.x < E) g_cnt[threadIdx.x] = 0;
}

__global__ void xhalf_kernel(const float* __restrict__ x) {
    int idx = blockIdx.x * blockDim.x + threadIdx.x;
    if (idx >= (T * H) / 4) return;
    float4 v = *(const float4*)(x + (size_t)idx * 4);
    uint2 o = make_uint2(pk2(v.x, v.y), pk2(v.z, v.w));
    *(uint2*)(g_xh + (size_t)idx * 4) = o;
}

__global__ void router_kernel(const float* __restrict__ x,
                              const float* __restrict__ gw,
                              const float* __restrict__ gb) {
    int t = blockIdx.x;
    __shared__ float xs[H];
    __shared__ float logit[E];
    for (int i = threadIdx.x; i < H; i += blockDim.x) xs[i] = x[(size_t)t * H + i];
    __syncthreads();
    int warp = threadIdx.x >> 5, lane = threadIdx.x & 31;
    for (int e = warp; e < E; e += 4) {
        const float* w = gw + (size_t)e * H;
        float s = 0.f;
        for (int i = lane; i < H; i += 32) s += xs[i] * w[i];
        #pragma unroll
        for (int o = 16; o; o >>= 1) s += __shfl_xor_sync(0xffffffffu, s, o);
        if (lane == 0) logit[e] = s;
    }
    __syncthreads();
    if (threadIdx.x == 0) {
        float sc[E], ss[E];
        #pragma unroll
        for (int e = 0; e < E; e++) {
            float s = 1.f / (1.f + expf(-logit[e]));
            ss[e] = s;
            sc[e] = s + gb[e];
        }
        float gsc[G];
        #pragma unroll
        for (int g = 0; g < G; g++) {
            float m1 = -1e30f, m2 = -1e30f;
            #pragma unroll
            for (int j = 0; j < 4; j++) {
                float v = sc[g * 4 + j];
                if (v > m1) { m2 = m1; m1 = v; } else if (v > m2) m2 = v;
            }
            gsc[g] = m1 + m2;
        }
        bool gsel[G];
        #pragma unroll
        for (int g = 0; g < G; g++) gsel[g] = false;
        for (int r = 0; r < TOPKG; r++) {
            int best = -1; float bv = -1e30f;
            for (int g = 0; g < G; g++)
                if (!gsel[g] && gsc[g] > bv) { bv = gsc[g]; best = g; }
            gsel[best] = true;
        }
        bool esel[E];
        #pragma unroll
        for (int e = 0; e < E; e++) esel[e] = false;
        int ids[KSEL];
        for (int r = 0; r < KSEL; r++) {
            int best = -1; float bv = -1e30f;
            for (int e = 0; e < E; e++) {
                if (esel[e] || !gsel[e >> 2]) continue;
                if (sc[e] > bv) { bv = sc[e]; best = e; }
            }
            esel[best] = true; ids[r] = best;
        }
        float w[KSEL], wsum = 0.f;
        for (int r = 0; r < KSEL; r++) { w[r] = ss[ids[r]]; wsum += w[r]; }
        float inv = 1.f / wsum;
        for (int r = 0; r < KSEL; r++) {
            g_topk_w[t * KSEL + r] = w[r] * inv;
            g_topk_id[t * KSEL + r] = ids[r];
            atomicAdd(&g_cnt[ids[r]], 1);
        }
    }
}

__global__ void scan_kernel() {
    if (threadIdx.x == 0) {
        int run = 0;
        for (int e = 0; e < E; e++) {
            g_off[e] = run;
            g_cur[e] = run;
            run += g_cnt[e];
        }
    }
}

__global__ void fill_kernel() {
    int a = blockIdx.x * blockDim.x + threadIdx.x;
    if (a >= NA) return;
    int e = g_topk_id[a];
    int pos = atomicAdd(&g_cur[e], 1);
    g_alist[pos] = a;
}

// =====================================================================
// Fused gate_up GEMM + silu*mul(*wt) -> fp16 hidden.
// GRID: blockIdx.x = ROW tile (M), blockIdx.y = COL tile (N).
//  -> adjacent blocks share the same B slab => B weights hit L2 after 1 DRAM read.
// Block 128 rows x 128 hidden cols; K-chunk 32; 8 warps (2x4), warp 64x32.
// =====================================================================
#define ASTG_F 10240     // 128 * 80
#define SMEM_F (6*ASTG_F + 2048)

template<bool ROUTED>
__global__ void __launch_bounds__(256, 1)
gemm_gateup(const float* __restrict__ W)
{
    constexpr int NPER = ROUTED ? II : IS;
    constexpr int LDB  = 2 * NPER;
    constexpr int NC   = H / 32;

    extern __shared__ char smem[];
    const uint32_t sbase = smem_u32(smem);
    char* meta = smem + 6 * ASTG_F;
    const __half** rowptr = (const __half**)meta;     // 128 ptrs
    int* aidx = (int*)(meta + 1024);                  // 128 ints

    int n, off = 0;
    const float* Bb = W;
    if (ROUTED) {
        int e = blockIdx.z;
        n = g_cnt[e]; off = g_off[e];
        if ((int)(blockIdx.x * 128) >= n) return;     // row tile beyond count
        Bb = W + (size_t)e * (size_t)H * LDB;
    } else n = T;

    const int row0 = blockIdx.x * 128;                // M tile (innermost)
    const int col0 = blockIdx.y * 128;                // N tile
    const int tid = threadIdx.x;

    if (tid < 128) {
        int gr = row0 + tid;
        int a = -1;
        if (ROUTED && gr < n) a = g_alist[off + gr];
        int aa = (!ROUTED) ? gr : ((a >= 0 ? a : g_alist[off]) / KSEL);
        rowptr[tid] = g_xh + (size_t)aa * H;
        aidx[tid] = a;
    }
    __syncthreads();

    const int lane = tid & 31, wid = tid >> 5;
    const int wm = wid >> 2, wn = wid & 3;
    const int gg = lane >> 2, t4 = lane & 3;

    float bRg[4][4], bRu[4][4];
    float accg[4][4][4] = {}, accu[4][4][4] = {};

    auto cpA = [&](int k0, int s) {
        #pragma unroll
        for (int r = 0; r < 2; r++) {
            int u = tid + 256 * r;
            int m = u >> 2, kq = u & 3;
            cpasync16(sbase + s * ASTG_F + m * 80 + kq * 16, rowptr[m] + k0 + kq * 8);
        }
    };
    auto ldgB = [&](int k0) {
        #pragma unroll
        for (int r = 0; r < 4; r++) {
            int u = tid + 256 * r;
            int nn = u & 127, kg = u >> 7;   // kg 0..7 (k-groups of 4)
            const float* gp = Bb + (size_t)(k0 + kg * 4) * LDB + col0 + nn;
            #pragma unroll
            for (int j = 0; j < 4; j++) {
                bRg[r][j] = gp[(size_t)j * LDB];
                bRu[r][j] = gp[(size_t)j * LDB + NPER];
            }
        }
    };
    auto stsB = [&](int s) {
        char* Bg_ = smem + (2 + s) * ASTG_F;
        char* Bu_ = smem + (4 + s) * ASTG_F;
        #pragma unroll
        for (int r = 0; r < 4; r++) {
            int u = tid + 256 * r;
            int nn = u & 127, kg = u >> 7;
            *(uint2*)(Bg_ + nn * 80 + kg * 8) = make_uint2(pk2(bRg[r][0], bRg[r][1]), pk2(bRg[r][2], bRg[r][3]));
            *(uint2*)(Bu_ + nn * 80 + kg * 8) = make_uint2(pk2(bRu[r][0], bRu[r][1]), pk2(bRu[r][2], bRu[r][3]));
        }
    };
    const int lrA = (lane & 7) + ((lane >> 3) & 1) * 8;
    const int lkA = (lane >> 4) * 8;
    const int lrB = (lane & 7) + (lane >> 4) * 8;
    const int lkB = ((lane >> 3) & 1) * 8;
    auto comp = [&](int s) {
        const uint32_t Ab = sbase + s * ASTG_F;
        const uint32_t Bgb = sbase + (2 + s) * ASTG_F;
        const uint32_t Bub = sbase + (4 + s) * ASTG_F;
        #pragma unroll
        for (int ks = 0; ks < 2; ks++) {
            const int kh = ks * 16;
            uint32_t af[4][4];
            #pragma unroll
            for (int mt = 0; mt < 4; mt++)
                ldmx4(af[mt], Ab + (wm * 64 + mt * 16 + lrA) * 80 + (kh + lkA) * 2);
            uint32_t bfg[2][4], bfu[2][4];
            #pragma unroll
            for (int np = 0; np < 2; np++) {
                ldmx4(bfg[np], Bgb + (wn * 32 + np * 16 + lrB) * 80 + (kh + lkB) * 2);
                ldmx4(bfu[np], Bub + (wn * 32 + np * 16 + lrB) * 80 + (kh + lkB) * 2);
            }
            #pragma unroll
            for (int mt = 0; mt < 4; mt++)
                #pragma unroll
                for (int nt = 0; nt < 4; nt++) {
                    mma16(accg[mt][nt], af[mt], bfg[nt >> 1][(nt & 1) * 2], bfg[nt >> 1][(nt & 1) * 2 + 1]);
                    mma16(accu[mt][nt], af[mt], bfu[nt >> 1][(nt & 1) * 2], bfu[nt >> 1][(nt & 1) * 2 + 1]);
                }
        }
    };

    cpA(0, 0); cp_commit();
    ldgB(0);
    stsB(0);
    cp_wait0();
    __syncthreads();
    for (int c = 0; c < NC; c++) {
        if (c + 1 < NC) {
            cpA((c + 1) * 32, (c + 1) & 1); cp_commit();
            ldgB((c + 1) * 32);
        }
        comp(c & 1);
        if (c + 1 < NC) stsB((c + 1) & 1);
        cp_wait0();
        __syncthreads();
    }

    // epilogue: h = silu(g)*u*wt  -> fp16
    #pragma unroll
    for (int mt = 0; mt < 4; mt++) {
        #pragma unroll
        for (int hf = 0; hf < 2; hf++) {
            int r = wm * 64 + mt * 16 + gg + hf * 8;
            __half* drow = nullptr;
            float wt = 1.f;
            if (!ROUTED) drow = g_shh + (size_t)(row0 + r) * IS + col0;
            else {
                int a = aidx[r];
                if (a >= 0) { drow = g_hh + (size_t)a * II + col0; wt = g_topk_w[a]; }
            }
            if (drow) {
                #pragma unroll
                for (int nt = 0; nt < 4; nt++) {
                    int cc = wn * 32 + nt * 8 + t4 * 2;
                    float g0 = accg[mt][nt][hf * 2],     u0 = accu[mt][nt][hf * 2];
                    float g1 = accg[mt][nt][hf * 2 + 1], u1 = accu[mt][nt][hf * 2 + 1];
                    *(__half2*)(drow + cc) = __floats2half2_rn(silu(g0) * u0 * wt, silu(g1) * u1 * wt);
                }
            }
        }
    }
}

// =====================================================================
// Down-proj GEMM: A fp16 (cp.async), B fp32 w2/sw2 -> fp32 out.
// GRID: blockIdx.x = ROW tile, blockIdx.y = COL tile (B reuse via L2).
// Block 128x128, K-chunk 64, 8 warps (2x4), warp 64x32. Row stride 144B.
// =====================================================================
#define ASTG_D 18432     // 128 * 144
#define SMEM_D (4*ASTG_D + 2048)

template<bool ROUTED>
__global__ void __launch_bounds__(256, 1)
gemm_down(const float* __restrict__ W, float* __restrict__ Dout)
{
    constexpr int KTOT = ROUTED ? II : IS;
    constexpr int NC   = KTOT / 64;

    extern __shared__ char smem[];
    const uint32_t sbase = smem_u32(smem);
    char* meta = smem + 4 * ASTG_D;
    const __half** rowptr = (const __half**)meta;
    int* aidx = (int*)(meta + 1024);

    int n, off = 0;
    const float* Bb = W;
    if (ROUTED) {
        int e = blockIdx.z;
        n = g_cnt[e]; off = g_off[e];
        if ((int)(blockIdx.x * 128) >= n) return;
        Bb = W + (size_t)e * (size_t)II * H;
    } else n = T;

    const int row0 = blockIdx.x * 128;
    const int col0 = blockIdx.y * 128;
    const int tid = threadIdx.x;

    if (tid < 128) {
        int gr = row0 + tid;
        int a = -1;
        const __half* p;
        if (!ROUTED) p = g_shh + (size_t)gr * IS;
        else {
            if (gr < n) a = g_alist[off + gr];
            int aa = a >= 0 ? a : g_alist[off];
            p = g_hh + (size_t)aa * II;
        }
        rowptr[tid] = p;
        aidx[tid] = a;
    }
    __syncthreads();

    const int lane = tid & 31, wid = tid >> 5;
    const int wm = wid >> 2, wn = wid & 3;
    const int gg = lane >> 2, t4 = lane & 3;

    float bR[8][4];
    float acc[4][4][4] = {};

    auto cpA = [&](int k0, int s) {
        #pragma unroll
        for (int r = 0; r < 4; r++) {
            int u = tid + 256 * r;
            int m = u >> 3, kq = u & 7;
            cpasync16(sbase + s * ASTG_D + m * 144 + kq * 16, rowptr[m] + k0 + kq * 8);
        }
    };
    auto ldgB = [&](int k0) {
        #pragma unroll
        for (int r = 0; r < 8; r++) {
            int u = tid + 256 * r;
            int nn = u & 127, kg = u >> 7;   // 0..15
            const float* gp = Bb + (size_t)(k0 + kg * 4) * H + col0 + nn;
            #pragma unroll
            for (int j = 0; j < 4; j++) bR[r][j] = gp[(size_t)j * H];
        }
    };
    auto stsB = [&](int s) {
        char* B_ = smem + (2 + s) * ASTG_D;
        #pragma unroll
        for (int r = 0; r < 8; r++) {
            int u = tid + 256 * r;
            int nn = u & 127, kg = u >> 7;
            *(uint2*)(B_ + nn * 144 + kg * 8) = make_uint2(pk2(bR[r][0], bR[r][1]), pk2(bR[r][2], bR[r][3]));
        }
    };
    const int lrA = (lane & 7) + ((lane >> 3) & 1) * 8;
    const int lkA = (lane >> 4) * 8;
    const int lrB = (lane & 7) + (lane >> 4) * 8;
    const int lkB = ((lane >> 3) & 1) * 8;
    auto comp = [&](int s) {
        const uint32_t Ab = sbase + s * ASTG_D;
        const uint32_t Bbs = sbase + (2 + s) * ASTG_D;
        #pragma unroll
        for (int ks = 0; ks < 4; ks++) {
            const int kh = ks * 16;
            uint32_t af[4][4];
            #pragma unroll
            for (int mt = 0; mt < 4; mt++)
                ldmx4(af[mt], Ab + (wm * 64 + mt * 16 + lrA) * 144 + (kh + lkA) * 2);
            uint32_t bf[2][4];
            #pragma unroll
            for (int np = 0; np < 2; np++)
                ldmx4(bf[np], Bbs + (wn * 32 + np * 16 + lrB) * 144 + (kh + lkB) * 2);
            #pragma unroll
            for (int mt = 0; mt < 4; mt++)
                #pragma unroll
                for (int nt = 0; nt < 4; nt++)
                    mma16(acc[mt][nt], af[mt], bf[nt >> 1][(nt & 1) * 2], bf[nt >> 1][(nt & 1) * 2 + 1]);
        }
    };

    cpA(0, 0); cp_commit();
    ldgB(0);
    stsB(0);
    cp_wait0();
    __syncthreads();
    for (int c = 0; c < NC; c++) {
        if (c + 1 < NC) {
            cpA((c + 1) * 64, (c + 1) & 1); cp_commit();
            ldgB((c + 1) * 64);
        }
        comp(c & 1);
        if (c + 1 < NC) stsB((c + 1) & 1);
        cp_wait0();
        __syncthreads();
    }

    #pragma unroll
    for (int mt = 0; mt < 4; mt++) {
        #pragma unroll
        for (int hf = 0; hf < 2; hf++) {
            int r = wm * 64 + mt * 16 + gg + hf * 8;
            float* drow = nullptr;
            if (!ROUTED) drow = Dout + (size_t)(row0 + r) * H + col0;
            else { int a = aidx[r]; if (a >= 0) drow = g_y + (size_t)a * H + col0; }
            if (drow) {
                #pragma unroll
                for (int nt = 0; nt < 4; nt++) {
                    int cc = wn * 32 + nt * 8 + t4 * 2;
                    *(float2*)(drow + cc) =
                        make_float2(acc[mt][nt][hf * 2], acc[mt][nt][hf * 2 + 1]);
                }
            }
        }
    }
}

// ---------------- combine: out += SCALE * sum_k y ----------------
__global__ void combine_kernel(float* __restrict__ out) {
    int idx = blockIdx.x * blockDim.x + threadIdx.x;
    if (idx >= (T * H) / 4) return;
    int t = idx / (H / 4);
    int c4 = idx % (H / 4);
    float4 acc = make_float4(0.f, 0.f, 0.f, 0.f);
    #pragma unroll
    for (int k = 0; k < KSEL; k++) {
        const float4 v = *(const float4*)(g_y + (size_t)(t * KSEL + k) * H + c4 * 4);
        acc.x += v.x; acc.y += v.y; acc.z += v.z; acc.w += v.w;
    }
    float4* o = (float4*)(out + (size_t)t * H + c4 * 4);
    float4 cur = *o;
    cur.x += SCALEF * acc.x;
    cur.y += SCALEF * acc.y;
    cur.z += SCALEF * acc.z;
    cur.w += SCALEF * acc.w;
    *o = cur;
}

// ---------------- launch ----------------
extern "C" void kernel_launch(void* const* d_in, const int* in_sizes, int n_in,
                              void* d_out, int out_size) {
    const float* x   = (const float*)d_in[0];
    const float* gw  = (const float*)d_in[1];
    const float* gb  = (const float*)d_in[2];
    const float* w1  = (const float*)d_in[3];
    const float* w2  = (const float*)d_in[4];
    const float* sw1 = (const float*)d_in[5];
    const float* sw2 = (const float*)d_in[6];
    float* out = (float*)d_out;

    cudaFuncSetAttribute(gemm_gateup<true>,  cudaFuncAttributeMaxDynamicSharedMemorySize, SMEM_F);
    cudaFuncSetAttribute(gemm_gateup<false>, cudaFuncAttributeMaxDynamicSharedMemorySize, SMEM_F);
    cudaFuncSetAttribute(gemm_down<true>,    cudaFuncAttributeMaxDynamicSharedMemorySize, SMEM_D);
    cudaFuncSetAttribute(gemm_down<false>,   cudaFuncAttributeMaxDynamicSharedMemorySize, SMEM_D);

    reset_kernel<<<1, 32>>>();
    xhalf_kernel<<<((T * H / 4) + 255) / 256, 256>>>(x);
    router_kernel<<<T, 128>>>(x, gw, gb);
    scan_kernel<<<1, 32>>>();
    fill_kernel<<<(NA + 255) / 256, 256>>>();

    // shared expert (grid: x = row tiles, y = col tiles -> B slab reuse in-wave)
    gemm_gateup<false><<<dim3(T / 128, IS / 128, 1), 256, SMEM_F>>>(sw1);
    gemm_down<false><<<dim3(T / 128, H / 128, 1), 256, SMEM_D>>>(sw2, out);

    // routed experts
    gemm_gateup<true><<<dim3(16, II / 128, E), 256, SMEM_F>>>(w1);
    gemm_down<true><<<dim3(16, H / 128, E), 256, SMEM_D>>>(w2, nullptr);

    combine_kernel<<<((T * H / 4) + 255) / 256, 256>>>(out);
}

// round 7
// speedup vs baseline: 5.1454x; 1.0097x over previous
#include <cuda_runtime.h>
#include <cuda_fp16.h>
#include <math.h>
#include <stdint.h>

#define T 2048
#define H 2048
#define E 32
#define KSEL 6
#define G 8
#define TOPKG 4
#define II 1408
#define IS 2816
#define SCALEF 2.5f
#define NA (T*KSEL)   // 12288 assignments

// ---------------- scratch (allocation-free: __device__ globals) ----------------
__device__ float  g_topk_w[NA];
__device__ int    g_topk_id[NA];
__device__ int    g_cnt[E];
__device__ int    g_off[E];
__device__ int    g_cur[E];
__device__ int    g_alist[NA];
__device__ __half g_xh[(size_t)T * H];        // x in fp16 (8 MB)
__device__ __half g_hh[(size_t)NA * II];      // routed hidden fp16 (~35 MB)
__device__ __half g_shh[(size_t)T * IS];      // shared hidden fp16 (~12 MB)

// ---------------- helpers ----------------
__device__ __forceinline__ uint32_t smem_u32(const void* p) {
    uint32_t a;
    asm("{ .reg .u64 t; cvta.to.shared.u64 t, %1; cvt.u32.u64 %0, t; }" : "=r"(a) : "l"(p));
    return a;
}
__device__ __forceinline__ uint32_t pk2(float a, float b) {
    __half2 h = __floats2half2_rn(a, b);
    return *(uint32_t*)&h;
}
__device__ __forceinline__ void cpasync16(uint32_t dst, const void* src) {
    asm volatile("cp.async.cg.shared.global [%0], [%1], 16;" :: "r"(dst), "l"(src));
}
__device__ __forceinline__ void cp_commit() {
    asm volatile("cp.async.commit_group;" ::: "memory");
}
__device__ __forceinline__ void cp_wait0() {
    asm volatile("cp.async.wait_group 0;" ::: "memory");
}
__device__ __forceinline__ void ldmx4(uint32_t* r, uint32_t addr) {
    asm volatile("ldmatrix.sync.aligned.m8n8.x4.shared.b16 {%0,%1,%2,%3}, [%4];"
                 : "=r"(r[0]), "=r"(r[1]), "=r"(r[2]), "=r"(r[3]) : "r"(addr));
}
__device__ __forceinline__ void mma16(float* d, const uint32_t* a, uint32_t b0, uint32_t b1) {
    asm volatile(
        "mma.sync.aligned.m16n8k16.row.col.f32.f16.f16.f32 "
        "{%0,%1,%2,%3}, {%4,%5,%6,%7}, {%8,%9}, {%0,%1,%2,%3};"
        : "+f"(d[0]), "+f"(d[1]), "+f"(d[2]), "+f"(d[3])
        : "r"(a[0]), "r"(a[1]), "r"(a[2]), "r"(a[3]), "r"(b0), "r"(b1));
}
__device__ __forceinline__ float silu(float g) { return g / (1.f + expf(-g)); }

// ---------------- small kernels ----------------
__global__ void reset_kernel() {
    if (threadIdx.x < E) g_cnt[threadIdx.x] = 0;
}

__global__ void xhalf_kernel(const float* __restrict__ x) {
    int idx = blockIdx.x * blockDim.x + threadIdx.x;
    if (idx >= (T * H) / 4) return;
    float4 v = *(const float4*)(x + (size_t)idx * 4);
    uint2 o = make_uint2(pk2(v.x, v.y), pk2(v.z, v.w));
    *(uint2*)(g_xh + (size_t)idx * 4) = o;
}

__global__ void router_kernel(const float* __restrict__ x,
                              const float* __restrict__ gw,
                              const float* __restrict__ gb) {
    int t = blockIdx.x;
    __shared__ float xs[H];
    __shared__ float logit[E];
    for (int i = threadIdx.x; i < H; i += blockDim.x) xs[i] = x[(size_t)t * H + i];
    __syncthreads();
    int warp = threadIdx.x >> 5, lane = threadIdx.x & 31;
    for (int e = warp; e < E; e += 4) {
        const float* w = gw + (size_t)e * H;
        float s = 0.f;
        for (int i = lane; i < H; i += 32) s += xs[i] * w[i];
        #pragma unroll
        for (int o = 16; o; o >>= 1) s += __shfl_xor_sync(0xffffffffu, s, o);
        if (lane == 0) logit[e] = s;
    }
    __syncthreads();
    if (threadIdx.x == 0) {
        float sc[E], ss[E];
        #pragma unroll
        for (int e = 0; e < E; e++) {
            float s = 1.f / (1.f + expf(-logit[e]));
            ss[e] = s;
            sc[e] = s + gb[e];
        }
        float gsc[G];
        #pragma unroll
        for (int g = 0; g < G; g++) {
            float m1 = -1e30f, m2 = -1e30f;
            #pragma unroll
            for (int j = 0; j < 4; j++) {
                float v = sc[g * 4 + j];
                if (v > m1) { m2 = m1; m1 = v; } else if (v > m2) m2 = v;
            }
            gsc[g] = m1 + m2;
        }
        bool gsel[G];
        #pragma unroll
        for (int g = 0; g < G; g++) gsel[g] = false;
        for (int r = 0; r < TOPKG; r++) {
            int best = -1; float bv = -1e30f;
            for (int g = 0; g < G; g++)
                if (!gsel[g] && gsc[g] > bv) { bv = gsc[g]; best = g; }
            gsel[best] = true;
        }
        bool esel[E];
        #pragma unroll
        for (int e = 0; e < E; e++) esel[e] = false;
        int ids[KSEL];
        for (int r = 0; r < KSEL; r++) {
            int best = -1; float bv = -1e30f;
            for (int e = 0; e < E; e++) {
                if (esel[e] || !gsel[e >> 2]) continue;
                if (sc[e] > bv) { bv = sc[e]; best = e; }
            }
            esel[best] = true; ids[r] = best;
        }
        float w[KSEL], wsum = 0.f;
        for (int r = 0; r < KSEL; r++) { w[r] = ss[ids[r]]; wsum += w[r]; }
        float inv = 1.f / wsum;
        for (int r = 0; r < KSEL; r++) {
            g_topk_w[t * KSEL + r] = w[r] * inv;
            g_topk_id[t * KSEL + r] = ids[r];
            atomicAdd(&g_cnt[ids[r]], 1);
        }
    }
}

__global__ void scan_kernel() {
    if (threadIdx.x == 0) {
        int run = 0;
        for (int e = 0; e < E; e++) {
            g_off[e] = run;
            g_cur[e] = run;
            run += g_cnt[e];
        }
    }
}

__global__ void fill_kernel() {
    int a = blockIdx.x * blockDim.x + threadIdx.x;
    if (a >= NA) return;
    int e = g_topk_id[a];
    int pos = atomicAdd(&g_cur[e], 1);
    g_alist[pos] = a;
}

// =====================================================================
// Fused gate_up GEMM + silu*mul(*wt) -> fp16 hidden.
// Predicated MMA skip for rows beyond the expert's count (warp-uniform).
// Block 128x128; K-chunk 32; 8 warps (2x4), warp 64x32.
// =====================================================================
#define ASTG_F 10240     // 128 * 80
#define SMEM_F (6*ASTG_F + 2048)

template<bool ROUTED>
__global__ void __launch_bounds__(256, 1)
gemm_gateup(const float* __restrict__ W)
{
    constexpr int NPER = ROUTED ? II : IS;
    constexpr int LDB  = 2 * NPER;
    constexpr int NC   = H / 32;

    extern __shared__ char smem[];
    const uint32_t sbase = smem_u32(smem);
    char* meta = smem + 6 * ASTG_F;
    const __half** rowptr = (const __half**)meta;     // 128 ptrs
    int* aidx = (int*)(meta + 1024);                  // 128 ints

    int n, off = 0;
    const float* Bb = W;
    if (ROUTED) {
        int e = blockIdx.z;
        n = g_cnt[e]; off = g_off[e];
        if ((int)(blockIdx.x * 128) >= n) return;
        Bb = W + (size_t)e * (size_t)H * LDB;
    } else n = T;

    const int row0 = blockIdx.x * 128;
    const int col0 = blockIdx.y * 128;
    const int tid = threadIdx.x;
    const int nv = ROUTED ? min(128, n - row0) : 128;   // valid rows this tile

    if (tid < 128) {
        int gr = row0 + tid;
        int a = -1;
        if (ROUTED && gr < n) a = g_alist[off + gr];
        int aa = (!ROUTED) ? gr : ((a >= 0 ? a : g_alist[off]) / KSEL);
        rowptr[tid] = g_xh + (size_t)aa * H;
        aidx[tid] = a;
    }
    __syncthreads();

    const int lane = tid & 31, wid = tid >> 5;
    const int wm = wid >> 2, wn = wid & 3;
    const int gg = lane >> 2, t4 = lane & 3;

    float bRg[4][4], bRu[4][4];
    float accg[4][4][4] = {}, accu[4][4][4] = {};

    auto cpA = [&](int k0, int s) {
        #pragma unroll
        for (int r = 0; r < 2; r++) {
            int u = tid + 256 * r;
            int m = u >> 2, kq = u & 3;
            cpasync16(sbase + s * ASTG_F + m * 80 + kq * 16, rowptr[m] + k0 + kq * 8);
        }
    };
    auto ldgB = [&](int k0) {
        #pragma unroll
        for (int r = 0; r < 4; r++) {
            int u = tid + 256 * r;
            int nn = u & 127, kg = u >> 7;
            const float* gp = Bb + (size_t)(k0 + kg * 4) * LDB + col0 + nn;
            #pragma unroll
            for (int j = 0; j < 4; j++) {
                bRg[r][j] = gp[(size_t)j * LDB];
                bRu[r][j] = gp[(size_t)j * LDB + NPER];
            }
        }
    };
    auto stsB = [&](int s) {
        char* Bg_ = smem + (2 + s) * ASTG_F;
        char* Bu_ = smem + (4 + s) * ASTG_F;
        #pragma unroll
        for (int r = 0; r < 4; r++) {
            int u = tid + 256 * r;
            int nn = u & 127, kg = u >> 7;
            *(uint2*)(Bg_ + nn * 80 + kg * 8) = make_uint2(pk2(bRg[r][0], bRg[r][1]), pk2(bRg[r][2], bRg[r][3]));
            *(uint2*)(Bu_ + nn * 80 + kg * 8) = make_uint2(pk2(bRu[r][0], bRu[r][1]), pk2(bRu[r][2], bRu[r][3]));
        }
    };
    const int lrA = (lane & 7) + ((lane >> 3) & 1) * 8;
    const int lkA = (lane >> 4) * 8;
    const int lrB = (lane & 7) + (lane >> 4) * 8;
    const int lkB = ((lane >> 3) & 1) * 8;
    auto comp = [&](int s) {
        const uint32_t Ab = sbase + s * ASTG_F;
        const uint32_t Bgb = sbase + (2 + s) * ASTG_F;
        const uint32_t Bub = sbase + (4 + s) * ASTG_F;
        if (wm * 64 >= nv) return;                       // whole warp-half invalid
        #pragma unroll
        for (int ks = 0; ks < 2; ks++) {
            const int kh = ks * 16;
            uint32_t af[4][4];
            #pragma unroll
            for (int mt = 0; mt < 4; mt++)
                if (wm * 64 + mt * 16 < nv)
                    ldmx4(af[mt], Ab + (wm * 64 + mt * 16 + lrA) * 80 + (kh + lkA) * 2);
            uint32_t bfg[2][4], bfu[2][4];
            #pragma unroll
            for (int np = 0; np < 2; np++) {
                ldmx4(bfg[np], Bgb + (wn * 32 + np * 16 + lrB) * 80 + (kh + lkB) * 2);
                ldmx4(bfu[np], Bub + (wn * 32 + np * 16 + lrB) * 80 + (kh + lkB) * 2);
            }
            #pragma unroll
            for (int mt = 0; mt < 4; mt++) {
                if (wm * 64 + mt * 16 >= nv) continue;
                #pragma unroll
                for (int nt = 0; nt < 4; nt++) {
                    mma16(accg[mt][nt], af[mt], bfg[nt >> 1][(nt & 1) * 2], bfg[nt >> 1][(nt & 1) * 2 + 1]);
                    mma16(accu[mt][nt], af[mt], bfu[nt >> 1][(nt & 1) * 2], bfu[nt >> 1][(nt & 1) * 2 + 1]);
                }
            }
        }
    };

    cpA(0, 0); cp_commit();
    ldgB(0);
    stsB(0);
    cp_wait0();
    __syncthreads();
    for (int c = 0; c < NC; c++) {
        if (c + 1 < NC) {
            cpA((c + 1) * 32, (c + 1) & 1); cp_commit();
            ldgB((c + 1) * 32);
        }
        comp(c & 1);
        if (c + 1 < NC) stsB((c + 1) & 1);
        cp_wait0();
        __syncthreads();
    }

    // epilogue: h = silu(g)*u*wt  -> fp16
    #pragma unroll
    for (int mt = 0; mt < 4; mt++) {
        #pragma unroll
        for (int hf = 0; hf < 2; hf++) {
            int r = wm * 64 + mt * 16 + gg + hf * 8;
            __half* drow = nullptr;
            float wt = 1.f;
            if (!ROUTED) drow = g_shh + (size_t)(row0 + r) * IS + col0;
            else {
                int a = aidx[r];
                if (a >= 0) { drow = g_hh + (size_t)a * II + col0; wt = g_topk_w[a]; }
            }
            if (drow) {
                #pragma unroll
                for (int nt = 0; nt < 4; nt++) {
                    int cc = wn * 32 + nt * 8 + t4 * 2;
                    float g0 = accg[mt][nt][hf * 2],     u0 = accu[mt][nt][hf * 2];
                    float g1 = accg[mt][nt][hf * 2 + 1], u1 = accu[mt][nt][hf * 2 + 1];
                    *(__half2*)(drow + cc) = __floats2half2_rn(silu(g0) * u0 * wt, silu(g1) * u1 * wt);
                }
            }
        }
    }
}

// =====================================================================
// Down-proj GEMM: A fp16 (cp.async), B fp32 w2/sw2.
// ROUTED: epilogue fuses combine -> atomicAdd(out, SCALE*acc).
// Block 128x128, K-chunk 64, 8 warps (2x4), warp 64x32. Row stride 144B.
// =====================================================================
#define ASTG_D 18432     // 128 * 144
#define SMEM_D (4*ASTG_D + 2048)

template<bool ROUTED>
__global__ void __launch_bounds__(256, 1)
gemm_down(const float* __restrict__ W, float* __restrict__ Dout)
{
    constexpr int KTOT = ROUTED ? II : IS;
    constexpr int NC   = KTOT / 64;

    extern __shared__ char smem[];
    const uint32_t sbase = smem_u32(smem);
    char* meta = smem + 4 * ASTG_D;
    const __half** rowptr = (const __half**)meta;
    int* aidx = (int*)(meta + 1024);

    int n, off = 0;
    const float* Bb = W;
    if (ROUTED) {
        int e = blockIdx.z;
        n = g_cnt[e]; off = g_off[e];
        if ((int)(blockIdx.x * 128) >= n) return;
        Bb = W + (size_t)e * (size_t)II * H;
    } else n = T;

    const int row0 = blockIdx.x * 128;
    const int col0 = blockIdx.y * 128;
    const int tid = threadIdx.x;
    const int nv = ROUTED ? min(128, n - row0) : 128;

    if (tid < 128) {
        int gr = row0 + tid;
        int a = -1;
        const __half* p;
        if (!ROUTED) p = g_shh + (size_t)gr * IS;
        else {
            if (gr < n) a = g_alist[off + gr];
            int aa = a >= 0 ? a : g_alist[off];
            p = g_hh + (size_t)aa * II;
        }
        rowptr[tid] = p;
        aidx[tid] = a;
    }
    __syncthreads();

    const int lane = tid & 31, wid = tid >> 5;
    const int wm = wid >> 2, wn = wid & 3;
    const int gg = lane >> 2, t4 = lane & 3;

    float bR[8][4];
    float acc[4][4][4] = {};

    auto cpA = [&](int k0, int s) {
        #pragma unroll
        for (int r = 0; r < 4; r++) {
            int u = tid + 256 * r;
            int m = u >> 3, kq = u & 7;
            cpasync16(sbase + s * ASTG_D + m * 144 + kq * 16, rowptr[m] + k0 + kq * 8);
        }
    };
    auto ldgB = [&](int k0) {
        #pragma unroll
        for (int r = 0; r < 8; r++) {
            int u = tid + 256 * r;
            int nn = u & 127, kg = u >> 7;
            const float* gp = Bb + (size_t)(k0 + kg * 4) * H + col0 + nn;
            #pragma unroll
            for (int j = 0; j < 4; j++) bR[r][j] = gp[(size_t)j * H];
        }
    };
    auto stsB = [&](int s) {
        char* B_ = smem + (2 + s) * ASTG_D;
        #pragma unroll
        for (int r = 0; r < 8; r++) {
            int u = tid + 256 * r;
            int nn = u & 127, kg = u >> 7;
            *(uint2*)(B_ + nn * 144 + kg * 8) = make_uint2(pk2(bR[r][0], bR[r][1]), pk2(bR[r][2], bR[r][3]));
        }
    };
    const int lrA = (lane & 7) + ((lane >> 3) & 1) * 8;
    const int lkA = (lane >> 4) * 8;
    const int lrB = (lane & 7) + (lane >> 4) * 8;
    const int lkB = ((lane >> 3) & 1) * 8;
    auto comp = [&](int s) {
        const uint32_t Ab = sbase + s * ASTG_D;
        const uint32_t Bbs = sbase + (2 + s) * ASTG_D;
        if (wm * 64 >= nv) return;
        #pragma unroll
        for (int ks = 0; ks < 4; ks++) {
            const int kh = ks * 16;
            uint32_t af[4][4];
            #pragma unroll
            for (int mt = 0; mt < 4; mt++)
                if (wm * 64 + mt * 16 < nv)
                    ldmx4(af[mt], Ab + (wm * 64 + mt * 16 + lrA) * 144 + (kh + lkA) * 2);
            uint32_t bf[2][4];
            #pragma unroll
            for (int np = 0; np < 2; np++)
                ldmx4(bf[np], Bbs + (wn * 32 + np * 16 + lrB) * 144 + (kh + lkB) * 2);
            #pragma unroll
            for (int mt = 0; mt < 4; mt++) {
                if (wm * 64 + mt * 16 >= nv) continue;
                #pragma unroll
                for (int nt = 0; nt < 4; nt++)
                    mma16(acc[mt][nt], af[mt], bf[nt >> 1][(nt & 1) * 2], bf[nt >> 1][(nt & 1) * 2 + 1]);
            }
        }
    };

    cpA(0, 0); cp_commit();
    ldgB(0);
    stsB(0);
    cp_wait0();
    __syncthreads();
    for (int c = 0; c < NC; c++) {
        if (c + 1 < NC) {
            cpA((c + 1) * 64, (c + 1) & 1); cp_commit();
            ldgB((c + 1) * 64);
        }
        comp(c & 1);
        if (c + 1 < NC) stsB((c + 1) & 1);
        cp_wait0();
        __syncthreads();
    }

    #pragma unroll
    for (int mt = 0; mt < 4; mt++) {
        #pragma unroll
        for (int hf = 0; hf < 2; hf++) {
            int r = wm * 64 + mt * 16 + gg + hf * 8;
            if (!ROUTED) {
                float* drow = Dout + (size_t)(row0 + r) * H + col0;
                #pragma unroll
                for (int nt = 0; nt < 4; nt++) {
                    int cc = wn * 32 + nt * 8 + t4 * 2;
                    *(float2*)(drow + cc) =
                        make_float2(acc[mt][nt][hf * 2], acc[mt][nt][hf * 2 + 1]);
                }
            } else {
                int a = aidx[r];
                if (a >= 0) {
                    float* drow = Dout + (size_t)(a / KSEL) * H + col0;
                    #pragma unroll
                    for (int nt = 0; nt < 4; nt++) {
                        int cc = wn * 32 + nt * 8 + t4 * 2;
                        atomicAdd(drow + cc,     SCALEF * acc[mt][nt][hf * 2]);
                        atomicAdd(drow + cc + 1, SCALEF * acc[mt][nt][hf * 2 + 1]);
                    }
                }
            }
        }
    }
}

// ---------------- launch ----------------
extern "C" void kernel_launch(void* const* d_in, const int* in_sizes, int n_in,
                              void* d_out, int out_size) {
    const float* x   = (const float*)d_in[0];
    const float* gw  = (const float*)d_in[1];
    const float* gb  = (const float*)d_in[2];
    const float* w1  = (const float*)d_in[3];
    const float* w2  = (const float*)d_in[4];
    const float* sw1 = (const float*)d_in[5];
    const float* sw2 = (const float*)d_in[6];
    float* out = (float*)d_out;

    cudaFuncSetAttribute(gemm_gateup<true>,  cudaFuncAttributeMaxDynamicSharedMemorySize, SMEM_F);
    cudaFuncSetAttribute(gemm_gateup<false>, cudaFuncAttributeMaxDynamicSharedMemorySize, SMEM_F);
    cudaFuncSetAttribute(gemm_down<true>,    cudaFuncAttributeMaxDynamicSharedMemorySize, SMEM_D);
    cudaFuncSetAttribute(gemm_down<false>,   cudaFuncAttributeMaxDynamicSharedMemorySize, SMEM_D);

    reset_kernel<<<1, 32>>>();
    xhalf_kernel<<<((T * H / 4) + 255) / 256, 256>>>(x);
    router_kernel<<<T, 128>>>(x, gw, gb);
    scan_kernel<<<1, 32>>>();
    fill_kernel<<<(NA + 255) / 256, 256>>>();

    // shared expert (writes full out)
    gemm_gateup<false><<<dim3(T / 128, IS / 128, 1), 256, SMEM_F>>>(sw1);
    gemm_down<false><<<dim3(T / 128, H / 128, 1), 256, SMEM_D>>>(sw2, out);

    // routed experts (down-proj atomically accumulates SCALE*y into out)
    gemm_gateup<true><<<dim3(16, II / 128, E), 256, SMEM_F>>>(w1);
    gemm_down<true><<<dim3(16, H / 128, E), 256, SMEM_D>>>(w2, out);
}

// round 9
// speedup vs baseline: 5.3293x; 1.0357x over previous
#include <cuda_runtime.h>
#include <cuda_fp16.h>
#include <math.h>
#include <stdint.h>

#define T 2048
#define H 2048
#define E 32
#define KSEL 6
#define G 8
#define TOPKG 4
#define II 1408
#define IS 2816
#define SCALEF 2.5f
#define NA (T*KSEL)   // 12288 assignments

// ---------------- scratch (allocation-free: __device__ globals) ----------------
__device__ float  g_topk_w[NA];
__device__ int    g_topk_id[NA];
__device__ int    g_cnt[E];
__device__ int    g_off[E];
__device__ int    g_cur[E];
__device__ int    g_alist[NA];
__device__ __half g_xh[(size_t)T * H];        // x in fp16 (8 MB)
__device__ __half g_hh[(size_t)NA * II];      // routed hidden fp16 (~35 MB)
__device__ __half g_shh[(size_t)T * IS];      // shared hidden fp16 (~12 MB)

// ---------------- helpers ----------------
__device__ __forceinline__ uint32_t smem_u32(const void* p) {
    uint32_t a;
    asm("{ .reg .u64 t; cvta.to.shared.u64 t, %1; cvt.u32.u64 %0, t; }" : "=r"(a) : "l"(p));
    return a;
}
__device__ __forceinline__ uint32_t pk2(float a, float b) {
    __half2 h = __floats2half2_rn(a, b);
    return *(uint32_t*)&h;
}
__device__ __forceinline__ void cpasync16(uint32_t dst, const void* src) {
    asm volatile("cp.async.cg.shared.global [%0], [%1], 16;" :: "r"(dst), "l"(src));
}
__device__ __forceinline__ void cp_commit() {
    asm volatile("cp.async.commit_group;" ::: "memory");
}
__device__ __forceinline__ void cp_wait0() {
    asm volatile("cp.async.wait_group 0;" ::: "memory");
}
__device__ __forceinline__ void ldmx4(uint32_t* r, uint32_t addr) {
    asm volatile("ldmatrix.sync.aligned.m8n8.x4.shared.b16 {%0,%1,%2,%3}, [%4];"
                 : "=r"(r[0]), "=r"(r[1]), "=r"(r[2]), "=r"(r[3]) : "r"(addr));
}
__device__ __forceinline__ void ldmx4t(uint32_t* r, uint32_t addr) {
    asm volatile("ldmatrix.sync.aligned.m8n8.x4.trans.shared.b16 {%0,%1,%2,%3}, [%4];"
                 : "=r"(r[0]), "=r"(r[1]), "=r"(r[2]), "=r"(r[3]) : "r"(addr));
}
__device__ __forceinline__ void mma16(float* d, const uint32_t* a, uint32_t b0, uint32_t b1) {
    asm volatile(
        "mma.sync.aligned.m16n8k16.row.col.f32.f16.f16.f32 "
        "{%0,%1,%2,%3}, {%4,%5,%6,%7}, {%8,%9}, {%0,%1,%2,%3};"
        : "+f"(d[0]), "+f"(d[1]), "+f"(d[2]), "+f"(d[3])
        : "r"(a[0]), "r"(a[1]), "r"(a[2]), "r"(a[3]), "r"(b0), "r"(b1));
}
__device__ __forceinline__ float silu(float g) { return g / (1.f + expf(-g)); }

// ---------------- small kernels ----------------
__global__ void xhalf_kernel(const float* __restrict__ x) {
    int idx = blockIdx.x * blockDim.x + threadIdx.x;
    if (blockIdx.x == 0 && threadIdx.x < E) g_cnt[threadIdx.x] = 0;
    if (idx >= (T * H) / 4) return;
    float4 v = *(const float4*)(x + (size_t)idx * 4);
    uint2 o = make_uint2(pk2(v.x, v.y), pk2(v.z, v.w));
    *(uint2*)(g_xh + (size_t)idx * 4) = o;
}

__global__ void router_kernel(const float* __restrict__ x,
                              const float* __restrict__ gw,
                              const float* __restrict__ gb) {
    int t = blockIdx.x;
    __shared__ float xs[H];
    __shared__ float logit[E];
    for (int i = threadIdx.x; i < H; i += blockDim.x) xs[i] = x[(size_t)t * H + i];
    __syncthreads();
    int warp = threadIdx.x >> 5, lane = threadIdx.x & 31;
    for (int e = warp; e < E; e += 4) {
        const float* w = gw + (size_t)e * H;
        float s = 0.f;
        for (int i = lane; i < H; i += 32) s += xs[i] * w[i];
        #pragma unroll
        for (int o = 16; o; o >>= 1) s += __shfl_xor_sync(0xffffffffu, s, o);
        if (lane == 0) logit[e] = s;
    }
    __syncthreads();
    if (threadIdx.x == 0) {
        float sc[E], ss[E];
        #pragma unroll
        for (int e = 0; e < E; e++) {
            float s = 1.f / (1.f + expf(-logit[e]));
            ss[e] = s;
            sc[e] = s + gb[e];
        }
        float gsc[G];
        #pragma unroll
        for (int g = 0; g < G; g++) {
            float m1 = -1e30f, m2 = -1e30f;
            #pragma unroll
            for (int j = 0; j < 4; j++) {
                float v = sc[g * 4 + j];
                if (v > m1) { m2 = m1; m1 = v; } else if (v > m2) m2 = v;
            }
            gsc[g] = m1 + m2;
        }
        bool gsel[G];
        #pragma unroll
        for (int g = 0; g < G; g++) gsel[g] = false;
        for (int r = 0; r < TOPKG; r++) {
            int best = -1; float bv = -1e30f;
            for (int g = 0; g < G; g++)
                if (!gsel[g] && gsc[g] > bv) { bv = gsc[g]; best = g; }
            gsel[best] = true;
        }
        bool esel[E];
        #pragma unroll
        for (int e = 0; e < E; e++) esel[e] = false;
        int ids[KSEL];
        for (int r = 0; r < KSEL; r++) {
            int best = -1; float bv = -1e30f;
            for (int e = 0; e < E; e++) {
                if (esel[e] || !gsel[e >> 2]) continue;
                if (sc[e] > bv) { bv = sc[e]; best = e; }
            }
            esel[best] = true; ids[r] = best;
        }
        float w[KSEL], wsum = 0.f;
        for (int r = 0; r < KSEL; r++) { w[r] = ss[ids[r]]; wsum += w[r]; }
        float inv = 1.f / wsum;
        for (int r = 0; r < KSEL; r++) {
            g_topk_w[t * KSEL + r] = w[r] * inv;
            g_topk_id[t * KSEL + r] = ids[r];
            atomicAdd(&g_cnt[ids[r]], 1);
        }
    }
}

__global__ void scan_kernel() {
    if (threadIdx.x == 0) {
        int run = 0;
        for (int e = 0; e < E; e++) {
            g_off[e] = run;
            g_cur[e] = run;
            run += g_cnt[e];
        }
    }
}

__global__ void fill_kernel() {
    int a = blockIdx.x * blockDim.x + threadIdx.x;
    if (a >= NA) return;
    int e = g_topk_id[a];
    int pos = atomicAdd(&g_cur[e], 1);
    g_alist[pos] = a;
}

// =====================================================================
// Fused gate_up GEMM + silu*mul(*wt) -> fp16 hidden.
// B smem layout [k][n] (272B row stride) + ldmatrix.trans fragments.
// B gmem loads: coalesced float4 along N. Block 128x128; K-chunk 32.
// =====================================================================
#define ASTG_FA 10240        // A stage: 128 * 80
#define BSTG_F  17408        // B stage: 2 tiles * 32 * 272
#define BOFF_F  (2*ASTG_FA)  // B base
#define SMEM_F  (2*ASTG_FA + 2*BSTG_F + 2048)

template<bool ROUTED>
__global__ void __launch_bounds__(256, 1)
gemm_gateup(const float* __restrict__ W)
{
    constexpr int NPER = ROUTED ? II : IS;
    constexpr int LDB  = 2 * NPER;
    constexpr int NC   = H / 32;

    extern __shared__ char smem[];
    const uint32_t sbase = smem_u32(smem);
    char* meta = smem + 2 * ASTG_FA + 2 * BSTG_F;
    const __half** rowptr = (const __half**)meta;     // 128 ptrs
    int* aidx = (int*)(meta + 1024);                  // 128 ints

    int n, off = 0;
    const float* Bb = W;
    if (ROUTED) {
        int e = blockIdx.z;
        n = g_cnt[e]; off = g_off[e];
        if ((int)(blockIdx.x * 128) >= n) return;
        Bb = W + (size_t)e * (size_t)H * LDB;
    } else n = T;

    const int row0 = blockIdx.x * 128;
    const int col0 = blockIdx.y * 128;
    const int tid = threadIdx.x;
    const int nv = ROUTED ? min(128, n - row0) : 128;

    if (tid < 128) {
        int gr = row0 + tid;
        int a = -1;
        if (ROUTED && gr < n) a = g_alist[off + gr];
        int aa = (!ROUTED) ? gr : ((a >= 0 ? a : g_alist[off]) / KSEL);
        rowptr[tid] = g_xh + (size_t)aa * H;
        aidx[tid] = a;
    }
    __syncthreads();

    const int lane = tid & 31, wid = tid >> 5;
    const int wm = wid >> 2, wn = wid & 3;
    const int gg = lane >> 2, t4 = lane & 3;

    float4 bF[8];                    // 8 float4 B loads per chunk
    float accg[4][4][4] = {}, accu[4][4][4] = {};

    auto cpA = [&](int k0, int s) {
        #pragma unroll
        for (int r = 0; r < 2; r++) {
            int u = tid + 256 * r;
            int m = u >> 2, kq = u & 3;
            cpasync16(sbase + s * ASTG_FA + m * 80 + kq * 16, rowptr[m] + k0 + kq * 8);
        }
    };
    // B: 2 tiles (gate, up), each [32 k][128 n] fp32 -> 2048 float4 total
    auto ldgB = [&](int k0) {
        #pragma unroll
        for (int r = 0; r < 8; r++) {
            int u = tid + 256 * r;
            int tile = u >> 10;            // 0 = gate, 1 = up
            int k = (u >> 5) & 31, ng = u & 31;
            const float* gp = Bb + (size_t)(k0 + k) * LDB + tile * NPER + col0 + ng * 4;
            bF[r] = *(const float4*)gp;
        }
    };
    auto stsB = [&](int s) {
        char* B_ = smem + BOFF_F + s * BSTG_F;
        #pragma unroll
        for (int r = 0; r < 8; r++) {
            int u = tid + 256 * r;
            int tile = u >> 10;
            int k = (u >> 5) & 31, ng = u & 31;
            *(uint2*)(B_ + tile * 8704 + k * 272 + ng * 8) =
                make_uint2(pk2(bF[r].x, bF[r].y), pk2(bF[r].z, bF[r].w));
        }
    };
    const int lrA = (lane & 7) + ((lane >> 3) & 1) * 8;
    const int lkA = (lane >> 4) * 8;
    const int kBo = (lane & 7) + ((lane >> 3) & 1) * 8;   // k within 16 (trans)
    const int nBo = (lane >> 4) * 8;                      // n offset 0/8
    auto comp = [&](int s) {
        const uint32_t Ab = sbase + s * ASTG_FA;
        const uint32_t Bgb = sbase + BOFF_F + s * BSTG_F;
        const uint32_t Bub = Bgb + 8704;
        if (wm * 64 >= nv) return;
        #pragma unroll
        for (int ks = 0; ks < 2; ks++) {
            const int kh = ks * 16;
            uint32_t af[4][4];
            #pragma unroll
            for (int mt = 0; mt < 4; mt++)
                if (wm * 64 + mt * 16 < nv)
                    ldmx4(af[mt], Ab + (wm * 64 + mt * 16 + lrA) * 80 + (kh + lkA) * 2);
            uint32_t bfg[2][4], bfu[2][4];
            #pragma unroll
            for (int np = 0; np < 2; np++) {
                uint32_t co = (wn * 32 + np * 16 + nBo) * 2;
                ldmx4t(bfg[np], Bgb + (kh + kBo) * 272 + co);
                ldmx4t(bfu[np], Bub + (kh + kBo) * 272 + co);
            }
            #pragma unroll
            for (int mt = 0; mt < 4; mt++) {
                if (wm * 64 + mt * 16 >= nv) continue;
                #pragma unroll
                for (int nt = 0; nt < 4; nt++) {
                    mma16(accg[mt][nt], af[mt], bfg[nt >> 1][(nt & 1) * 2], bfg[nt >> 1][(nt & 1) * 2 + 1]);
                    mma16(accu[mt][nt], af[mt], bfu[nt >> 1][(nt & 1) * 2], bfu[nt >> 1][(nt & 1) * 2 + 1]);
                }
            }
        }
    };

    cpA(0, 0); cp_commit();
    ldgB(0);
    stsB(0);
    cp_wait0();
    __syncthreads();
    for (int c = 0; c < NC; c++) {
        if (c + 1 < NC) {
            cpA((c + 1) * 32, (c + 1) & 1); cp_commit();
            ldgB((c + 1) * 32);
        }
        comp(c & 1);
        if (c + 1 < NC) stsB((c + 1) & 1);
        cp_wait0();
        __syncthreads();
    }

    // epilogue: h = silu(g)*u*wt  -> fp16
    #pragma unroll
    for (int mt = 0; mt < 4; mt++) {
        #pragma unroll
        for (int hf = 0; hf < 2; hf++) {
            int r = wm * 64 + mt * 16 + gg + hf * 8;
            __half* drow = nullptr;
            float wt = 1.f;
            if (!ROUTED) drow = g_shh + (size_t)(row0 + r) * IS + col0;
            else {
                int a = aidx[r];
                if (a >= 0) { drow = g_hh + (size_t)a * II + col0; wt = g_topk_w[a]; }
            }
            if (drow) {
                #pragma unroll
                for (int nt = 0; nt < 4; nt++) {
                    int cc = wn * 32 + nt * 8 + t4 * 2;
                    float g0 = accg[mt][nt][hf * 2],     u0 = accu[mt][nt][hf * 2];
                    float g1 = accg[mt][nt][hf * 2 + 1], u1 = accu[mt][nt][hf * 2 + 1];
                    *(__half2*)(drow + cc) = __floats2half2_rn(silu(g0) * u0 * wt, silu(g1) * u1 * wt);
                }
            }
        }
    }
}

// =====================================================================
// Down-proj GEMM: A fp16 (cp.async), B fp32 [k][n] smem + ldmatrix.trans.
// ROUTED: epilogue fuses combine -> atomicAdd(out, SCALE*acc).
// Block 128x128, K-chunk 64. A stride 144B, B stride 272B.
// =====================================================================
#define ASTG_DA 18432        // A stage: 128 * 144
#define BSTG_D  17408        // B stage: 64 * 272
#define BOFF_D  (2*ASTG_DA)
#define SMEM_D  (2*ASTG_DA + 2*BSTG_D + 2048)

template<bool ROUTED>
__global__ void __launch_bounds__(256, 1)
gemm_down(const float* __restrict__ W, float* __restrict__ Dout)
{
    constexpr int KTOT = ROUTED ? II : IS;
    constexpr int NC   = KTOT / 64;

    extern __shared__ char smem[];
    const uint32_t sbase = smem_u32(smem);
    char* meta = smem + 2 * ASTG_DA + 2 * BSTG_D;
    const __half** rowptr = (const __half**)meta;
    int* aidx = (int*)(meta + 1024);

    int n, off = 0;
    const float* Bb = W;
    if (ROUTED) {
        int e = blockIdx.z;
        n = g_cnt[e]; off = g_off[e];
        if ((int)(blockIdx.x * 128) >= n) return;
        Bb = W + (size_t)e * (size_t)II * H;
    } else n = T;

    const int row0 = blockIdx.x * 128;
    const int col0 = blockIdx.y * 128;
    const int tid = threadIdx.x;
    const int nv = ROUTED ? min(128, n - row0) : 128;

    if (tid < 128) {
        int gr = row0 + tid;
        int a = -1;
        const __half* p;
        if (!ROUTED) p = g_shh + (size_t)gr * IS;
        else {
            if (gr < n) a = g_alist[off + gr];
            int aa = a >= 0 ? a : g_alist[off];
            p = g_hh + (size_t)aa * II;
        }
        rowptr[tid] = p;
        aidx[tid] = a;
    }
    __syncthreads();

    const int lane = tid & 31, wid = tid >> 5;
    const int wm = wid >> 2, wn = wid & 3;
    const int gg = lane >> 2, t4 = lane & 3;

    float4 bF[8];
    float acc[4][4][4] = {};

    auto cpA = [&](int k0, int s) {
        #pragma unroll
        for (int r = 0; r < 4; r++) {
            int u = tid + 256 * r;
            int m = u >> 3, kq = u & 7;
            cpasync16(sbase + s * ASTG_DA + m * 144 + kq * 16, rowptr[m] + k0 + kq * 8);
        }
    };
    // B tile [64 k][128 n] fp32 = 2048 float4
    auto ldgB = [&](int k0) {
        #pragma unroll
        for (int r = 0; r < 8; r++) {
            int u = tid + 256 * r;
            int k = u >> 5, ng = u & 31;
            bF[r] = *(const float4*)(Bb + (size_t)(k0 + k) * H + col0 + ng * 4);
        }
    };
    auto stsB = [&](int s) {
        char* B_ = smem + BOFF_D + s * BSTG_D;
        #pragma unroll
        for (int r = 0; r < 8; r++) {
            int u = tid + 256 * r;
            int k = u >> 5, ng = u & 31;
            *(uint2*)(B_ + k * 272 + ng * 8) =
                make_uint2(pk2(bF[r].x, bF[r].y), pk2(bF[r].z, bF[r].w));
        }
    };
    const int lrA = (lane & 7) + ((lane >> 3) & 1) * 8;
    const int lkA = (lane >> 4) * 8;
    const int kBo = (lane & 7) + ((lane >> 3) & 1) * 8;
    const int nBo = (lane >> 4) * 8;
    auto comp = [&](int s) {
        const uint32_t Ab = sbase + s * ASTG_DA;
        const uint32_t Bbs = sbase + BOFF_D + s * BSTG_D;
        if (wm * 64 >= nv) return;
        #pragma unroll
        for (int ks = 0; ks < 4; ks++) {
            const int kh = ks * 16;
            uint32_t af[4][4];
            #pragma unroll
            for (int mt = 0; mt < 4; mt++)
                if (wm * 64 + mt * 16 < nv)
                    ldmx4(af[mt], Ab + (wm * 64 + mt * 16 + lrA) * 144 + (kh + lkA) * 2);
            uint32_t bf[2][4];
            #pragma unroll
            for (int np = 0; np < 2; np++)
                ldmx4t(bf[np], Bbs + (kh + kBo) * 272 + (wn * 32 + np * 16 + nBo) * 2);
            #pragma unroll
            for (int mt = 0; mt < 4; mt++) {
                if (wm * 64 + mt * 16 >= nv) continue;
                #pragma unroll
                for (int nt = 0; nt < 4; nt++)
                    mma16(acc[mt][nt], af[mt], bf[nt >> 1][(nt & 1) * 2], bf[nt >> 1][(nt & 1) * 2 + 1]);
            }
        }
    };

    cpA(0, 0); cp_commit();
    ldgB(0);
    stsB(0);
    cp_wait0();
    __syncthreads();
    for (int c = 0; c < NC; c++) {
        if (c + 1 < NC) {
            cpA((c + 1) * 64, (c + 1) & 1); cp_commit();
            ldgB((c + 1) * 64);
        }
        comp(c & 1);
        if (c + 1 < NC) stsB((c + 1) & 1);
        cp_wait0();
        __syncthreads();
    }

    #pragma unroll
    for (int mt = 0; mt < 4; mt++) {
        #pragma unroll
        for (int hf = 0; hf < 2; hf++) {
            int r = wm * 64 + mt * 16 + gg + hf * 8;
            if (!ROUTED) {
                float* drow = Dout + (size_t)(row0 + r) * H + col0;
                #pragma unroll
                for (int nt = 0; nt < 4; nt++) {
                    int cc = wn * 32 + nt * 8 + t4 * 2;
                    *(float2*)(drow + cc) =
                        make_float2(acc[mt][nt][hf * 2], acc[mt][nt][hf * 2 + 1]);
                }
            } else {
                int a = aidx[r];
                if (a >= 0) {
                    float* drow = Dout + (size_t)(a / KSEL) * H + col0;
                    #pragma unroll
                    for (int nt = 0; nt < 4; nt++) {
                        int cc = wn * 32 + nt * 8 + t4 * 2;
                        atomicAdd(drow + cc,     SCALEF * acc[mt][nt][hf * 2]);
                        atomicAdd(drow + cc + 1, SCALEF * acc[mt][nt][hf * 2 + 1]);
                    }
                }
            }
        }
    }
}

// ---------------- launch ----------------
extern "C" void kernel_launch(void* const* d_in, const int* in_sizes, int n_in,
                              void* d_out, int out_size) {
    const float* x   = (const float*)d_in[0];
    const float* gw  = (const float*)d_in[1];
    const float* gb  = (const float*)d_in[2];
    const float* w1  = (const float*)d_in[3];
    const float* w2  = (const float*)d_in[4];
    const float* sw1 = (const float*)d_in[5];
    const float* sw2 = (const float*)d_in[6];
    float* out = (float*)d_out;

    cudaFuncSetAttribute(gemm_gateup<true>,  cudaFuncAttributeMaxDynamicSharedMemorySize, SMEM_F);
    cudaFuncSetAttribute(gemm_gateup<false>, cudaFuncAttributeMaxDynamicSharedMemorySize, SMEM_F);
    cudaFuncSetAttribute(gemm_down<true>,    cudaFuncAttributeMaxDynamicSharedMemorySize, SMEM_D);
    cudaFuncSetAttribute(gemm_down<false>,   cudaFuncAttributeMaxDynamicSharedMemorySize, SMEM_D);

    xhalf_kernel<<<((T * H / 4) + 255) / 256, 256>>>(x);
    router_kernel<<<T, 128>>>(x, gw, gb);
    scan_kernel<<<1, 32>>>();
    fill_kernel<<<(NA + 255) / 256, 256>>>();

    // shared expert (writes full out)
    gemm_gateup<false><<<dim3(T / 128, IS / 128, 1), 256, SMEM_F>>>(sw1);
    gemm_down<false><<<dim3(T / 128, H / 128, 1), 256, SMEM_D>>>(sw2, out);

    // routed experts (down-proj atomically accumulates SCALE*y into out)
    gemm_gateup<true><<<dim3(16, II / 128, E), 256, SMEM_F>>>(w1);
    gemm_down<true><<<dim3(16, H / 128, E), 256, SMEM_D>>>(w2, out);
}

// round 10
// speedup vs baseline: 5.4549x; 1.0236x over previous
#include <cuda_runtime.h>
#include <cuda_fp16.h>
#include <math.h>
#include <stdint.h>

#define T 2048
#define H 2048
#define E 32
#define KSEL 6
#define G 8
#define TOPKG 4
#define II 1408
#define IS 2816
#define SCALEF 2.5f
#define NA (T*KSEL)   // 12288 assignments

// ---------------- scratch (allocation-free: __device__ globals) ----------------
__device__ float    g_topk_w[NA];
__device__ int      g_topk_id[NA];
__device__ int      g_cnt[E];
__device__ int      g_off[E];
__device__ int      g_cur[E];
__device__ int      g_alist[NA];
__device__ unsigned g_done;
__device__ __half   g_xh[(size_t)T * H];        // x in fp16 (8 MB)
__device__ __half   g_hh[(size_t)NA * II];      // routed hidden fp16 (~35 MB)
__device__ __half   g_shh[(size_t)T * IS];      // shared hidden fp16 (~12 MB)

// ---------------- helpers ----------------
__device__ __forceinline__ uint32_t smem_u32(const void* p) {
    uint32_t a;
    asm("{ .reg .u64 t; cvta.to.shared.u64 t, %1; cvt.u32.u64 %0, t; }" : "=r"(a) : "l"(p));
    return a;
}
__device__ __forceinline__ uint32_t pk2(float a, float b) {
    __half2 h = __floats2half2_rn(a, b);
    return *(uint32_t*)&h;
}
__device__ __forceinline__ void cpasync16(uint32_t dst, const void* src) {
    asm volatile("cp.async.cg.shared.global [%0], [%1], 16;" :: "r"(dst), "l"(src));
}
__device__ __forceinline__ void cp_commit() {
    asm volatile("cp.async.commit_group;" ::: "memory");
}
__device__ __forceinline__ void cp_wait0() {
    asm volatile("cp.async.wait_group 0;" ::: "memory");
}
__device__ __forceinline__ void ldmx4(uint32_t* r, uint32_t addr) {
    asm volatile("ldmatrix.sync.aligned.m8n8.x4.shared.b16 {%0,%1,%2,%3}, [%4];"
                 : "=r"(r[0]), "=r"(r[1]), "=r"(r[2]), "=r"(r[3]) : "r"(addr));
}
__device__ __forceinline__ void ldmx4t(uint32_t* r, uint32_t addr) {
    asm volatile("ldmatrix.sync.aligned.m8n8.x4.trans.shared.b16 {%0,%1,%2,%3}, [%4];"
                 : "=r"(r[0]), "=r"(r[1]), "=r"(r[2]), "=r"(r[3]) : "r"(addr));
}
__device__ __forceinline__ void mma16(float* d, const uint32_t* a, uint32_t b0, uint32_t b1) {
    asm volatile(
        "mma.sync.aligned.m16n8k16.row.col.f32.f16.f16.f32 "
        "{%0,%1,%2,%3}, {%4,%5,%6,%7}, {%8,%9}, {%0,%1,%2,%3};"
        : "+f"(d[0]), "+f"(d[1]), "+f"(d[2]), "+f"(d[3])
        : "r"(a[0]), "r"(a[1]), "r"(a[2]), "r"(a[3]), "r"(b0), "r"(b1));
}
__device__ __forceinline__ float silu(float g) { return g / (1.f + expf(-g)); }

// ---------------- small kernels ----------------
__global__ void xhalf_kernel(const float* __restrict__ x, float* __restrict__ out) {
    int idx = blockIdx.x * blockDim.x + threadIdx.x;
    if (blockIdx.x == 0 && threadIdx.x < E) g_cnt[threadIdx.x] = 0;
    if (blockIdx.x == 0 && threadIdx.x == 0) g_done = 0;
    if (idx >= (T * H) / 4) return;
    float4 v = *(const float4*)(x + (size_t)idx * 4);
    uint2 o = make_uint2(pk2(v.x, v.y), pk2(v.z, v.w));
    *(uint2*)(g_xh + (size_t)idx * 4) = o;
    *(float4*)(out + (size_t)idx * 4) = make_float4(0.f, 0.f, 0.f, 0.f);
}

__global__ void router_kernel(const float* __restrict__ x,
                              const float* __restrict__ gw,
                              const float* __restrict__ gb) {
    int t = blockIdx.x;
    __shared__ float xs[H];
    __shared__ float logit[E];
    for (int i = threadIdx.x; i < H; i += blockDim.x) xs[i] = x[(size_t)t * H + i];
    __syncthreads();
    int warp = threadIdx.x >> 5, lane = threadIdx.x & 31;
    for (int e = warp; e < E; e += 4) {
        const float* w = gw + (size_t)e * H;
        float s = 0.f;
        for (int i = lane; i < H; i += 32) s += xs[i] * w[i];
        #pragma unroll
        for (int o = 16; o; o >>= 1) s += __shfl_xor_sync(0xffffffffu, s, o);
        if (lane == 0) logit[e] = s;
    }
    __syncthreads();
    if (threadIdx.x == 0) {
        float sc[E], ss[E];
        #pragma unroll
        for (int e = 0; e < E; e++) {
            float s = 1.f / (1.f + expf(-logit[e]));
            ss[e] = s;
            sc[e] = s + gb[e];
        }
        float gsc[G];
        #pragma unroll
        for (int g = 0; g < G; g++) {
            float m1 = -1e30f, m2 = -1e30f;
            #pragma unroll
            for (int j = 0; j < 4; j++) {
                float v = sc[g * 4 + j];
                if (v > m1) { m2 = m1; m1 = v; } else if (v > m2) m2 = v;
            }
            gsc[g] = m1 + m2;
        }
        bool gsel[G];
        #pragma unroll
        for (int g = 0; g < G; g++) gsel[g] = false;
        for (int r = 0; r < TOPKG; r++) {
            int best = -1; float bv = -1e30f;
            for (int g = 0; g < G; g++)
                if (!gsel[g] && gsc[g] > bv) { bv = gsc[g]; best = g; }
            gsel[best] = true;
        }
        bool esel[E];
        #pragma unroll
        for (int e = 0; e < E; e++) esel[e] = false;
        int ids[KSEL];
        for (int r = 0; r < KSEL; r++) {
            int best = -1; float bv = -1e30f;
            for (int e = 0; e < E; e++) {
                if (esel[e] || !gsel[e >> 2]) continue;
                if (sc[e] > bv) { bv = sc[e]; best = e; }
            }
            esel[best] = true; ids[r] = best;
        }
        float w[KSEL], wsum = 0.f;
        for (int r = 0; r < KSEL; r++) { w[r] = ss[ids[r]]; wsum += w[r]; }
        float inv = 1.f / wsum;
        for (int r = 0; r < KSEL; r++) {
            g_topk_w[t * KSEL + r] = w[r] * inv;
            g_topk_id[t * KSEL + r] = ids[r];
            atomicAdd(&g_cnt[ids[r]], 1);
        }
        // last block performs the scan (threadfence + done-counter pattern)
        __threadfence();
        unsigned prev = atomicAdd(&g_done, 1u);
        if (prev == gridDim.x - 1) {
            int run = 0;
            for (int e = 0; e < E; e++) {
                g_off[e] = run;
                g_cur[e] = run;
                run += g_cnt[e];
            }
        }
    }
}

__global__ void fill_kernel() {
    int a = blockIdx.x * blockDim.x + threadIdx.x;
    if (a >= NA) return;
    int e = g_topk_id[a];
    int pos = atomicAdd(&g_cur[e], 1);
    g_alist[pos] = a;
}

// =====================================================================
// MERGED gate_up GEMM + silu*mul(*wt) -> fp16 hidden.
// blockIdx.z in [0,32]: z<32 = routed expert z, z==32 = shared expert.
// B smem [k][n] (272B stride) + ldmatrix.trans. Block 128x128; K-chunk 32.
// =====================================================================
#define ASTG_FA 10240        // A stage: 128 * 80
#define BSTG_F  17408        // B stage: 2 tiles * 32 * 272
#define BOFF_F  (2*ASTG_FA)
#define SMEM_F  (2*ASTG_FA + 2*BSTG_F + 2048)

__global__ void __launch_bounds__(256, 1)
gemm_gateup(const float* __restrict__ w1, const float* __restrict__ sw1)
{
    const bool routed = (blockIdx.z < 32);
    const int NPER = routed ? II : IS;
    const int LDB  = 2 * NPER;
    constexpr int NC = H / 32;

    if ((int)(blockIdx.y * 128) >= NPER) return;

    extern __shared__ char smem[];
    const uint32_t sbase = smem_u32(smem);
    char* meta = smem + 2 * ASTG_FA + 2 * BSTG_F;
    const __half** rowptr = (const __half**)meta;     // 128 ptrs
    int* aidx = (int*)(meta + 1024);                  // 128 ints

    int n, off = 0;
    const float* Bb;
    if (routed) {
        int e = blockIdx.z;
        n = g_cnt[e]; off = g_off[e];
        if ((int)(blockIdx.x * 128) >= n) return;
        Bb = w1 + (size_t)e * (size_t)H * (2 * II);
    } else { n = T; Bb = sw1; }

    const int row0 = blockIdx.x * 128;
    const int col0 = blockIdx.y * 128;
    const int tid = threadIdx.x;
    const int nv = routed ? min(128, n - row0) : 128;

    if (tid < 128) {
        int gr = row0 + tid;
        int a = -1;
        if (routed && gr < n) a = g_alist[off + gr];
        int aa = (!routed) ? gr : ((a >= 0 ? a : g_alist[off]) / KSEL);
        rowptr[tid] = g_xh + (size_t)aa * H;
        aidx[tid] = a;
    }
    __syncthreads();

    const int lane = tid & 31, wid = tid >> 5;
    const int wm = wid >> 2, wn = wid & 3;
    const int gg = lane >> 2, t4 = lane & 3;

    float4 bF[8];
    float accg[4][4][4] = {}, accu[4][4][4] = {};

    auto cpA = [&](int k0, int s) {
        #pragma unroll
        for (int r = 0; r < 2; r++) {
            int u = tid + 256 * r;
            int m = u >> 2, kq = u & 3;
            cpasync16(sbase + s * ASTG_FA + m * 80 + kq * 16, rowptr[m] + k0 + kq * 8);
        }
    };
    auto ldgB = [&](int k0) {
        #pragma unroll
        for (int r = 0; r < 8; r++) {
            int u = tid + 256 * r;
            int tile = u >> 10;            // 0 = gate, 1 = up
            int k = (u >> 5) & 31, ng = u & 31;
            const float* gp = Bb + (size_t)(k0 + k) * LDB + tile * NPER + col0 + ng * 4;
            bF[r] = *(const float4*)gp;
        }
    };
    auto stsB = [&](int s) {
        char* B_ = smem + BOFF_F + s * BSTG_F;
        #pragma unroll
        for (int r = 0; r < 8; r++) {
            int u = tid + 256 * r;
            int tile = u >> 10;
            int k = (u >> 5) & 31, ng = u & 31;
            *(uint2*)(B_ + tile * 8704 + k * 272 + ng * 8) =
                make_uint2(pk2(bF[r].x, bF[r].y), pk2(bF[r].z, bF[r].w));
        }
    };
    const int lrA = (lane & 7) + ((lane >> 3) & 1) * 8;
    const int lkA = (lane >> 4) * 8;
    const int kBo = (lane & 7) + ((lane >> 3) & 1) * 8;
    const int nBo = (lane >> 4) * 8;
    auto comp = [&](int s) {
        const uint32_t Ab = sbase + s * ASTG_FA;
        const uint32_t Bgb = sbase + BOFF_F + s * BSTG_F;
        const uint32_t Bub = Bgb + 8704;
        if (wm * 64 >= nv) return;
        #pragma unroll
        for (int ks = 0; ks < 2; ks++) {
            const int kh = ks * 16;
            uint32_t af[4][4];
            #pragma unroll
            for (int mt = 0; mt < 4; mt++)
                if (wm * 64 + mt * 16 < nv)
                    ldmx4(af[mt], Ab + (wm * 64 + mt * 16 + lrA) * 80 + (kh + lkA) * 2);
            uint32_t bfg[2][4], bfu[2][4];
            #pragma unroll
            for (int np = 0; np < 2; np++) {
                uint32_t co = (wn * 32 + np * 16 + nBo) * 2;
                ldmx4t(bfg[np], Bgb + (kh + kBo) * 272 + co);
                ldmx4t(bfu[np], Bub + (kh + kBo) * 272 + co);
            }
            #pragma unroll
            for (int mt = 0; mt < 4; mt++) {
                if (wm * 64 + mt * 16 >= nv) continue;
                #pragma unroll
                for (int nt = 0; nt < 4; nt++) {
                    mma16(accg[mt][nt], af[mt], bfg[nt >> 1][(nt & 1) * 2], bfg[nt >> 1][(nt & 1) * 2 + 1]);
                    mma16(accu[mt][nt], af[mt], bfu[nt >> 1][(nt & 1) * 2], bfu[nt >> 1][(nt & 1) * 2 + 1]);
                }
            }
        }
    };

    cpA(0, 0); cp_commit();
    ldgB(0);
    stsB(0);
    cp_wait0();
    __syncthreads();
    for (int c = 0; c < NC; c++) {
        if (c + 1 < NC) {
            cpA((c + 1) * 32, (c + 1) & 1); cp_commit();
            ldgB((c + 1) * 32);
        }
        comp(c & 1);
        if (c + 1 < NC) stsB((c + 1) & 1);
        cp_wait0();
        __syncthreads();
    }

    // epilogue: h = silu(g)*u*wt  -> fp16
    #pragma unroll
    for (int mt = 0; mt < 4; mt++) {
        #pragma unroll
        for (int hf = 0; hf < 2; hf++) {
            int r = wm * 64 + mt * 16 + gg + hf * 8;
            __half* drow = nullptr;
            float wt = 1.f;
            if (!routed) drow = g_shh + (size_t)(row0 + r) * IS + col0;
            else {
                int a = aidx[r];
                if (a >= 0) { drow = g_hh + (size_t)a * II + col0; wt = g_topk_w[a]; }
            }
            if (drow) {
                #pragma unroll
                for (int nt = 0; nt < 4; nt++) {
                    int cc = wn * 32 + nt * 8 + t4 * 2;
                    float g0 = accg[mt][nt][hf * 2],     u0 = accu[mt][nt][hf * 2];
                    float g1 = accg[mt][nt][hf * 2 + 1], u1 = accu[mt][nt][hf * 2 + 1];
                    *(__half2*)(drow + cc) = __floats2half2_rn(silu(g0) * u0 * wt, silu(g1) * u1 * wt);
                }
            }
        }
    }
}

// =====================================================================
// MERGED down-proj GEMM: z<32 routed (K=II), z==32 shared (K=IS).
// out pre-zeroed; BOTH paths atomicAdd (routed scaled by 2.5).
// Block 128x128, K-chunk 64. A stride 144B, B stride 272B.
// =====================================================================
#define ASTG_DA 18432        // A stage: 128 * 144
#define BSTG_D  17408        // B stage: 64 * 272
#define BOFF_D  (2*ASTG_DA)
#define SMEM_D  (2*ASTG_DA + 2*BSTG_D + 2048)

__global__ void __launch_bounds__(256, 1)
gemm_down(const float* __restrict__ w2, const float* __restrict__ sw2, float* __restrict__ Dout)
{
    const bool routed = (blockIdx.z < 32);
    const int KTOT = routed ? II : IS;
    const int NCr  = KTOT / 64;

    extern __shared__ char smem[];
    const uint32_t sbase = smem_u32(smem);
    char* meta = smem + 2 * ASTG_DA + 2 * BSTG_D;
    const __half** rowptr = (const __half**)meta;
    int* aidx = (int*)(meta + 1024);

    int n, off = 0;
    const float* Bb;
    if (routed) {
        int e = blockIdx.z;
        n = g_cnt[e]; off = g_off[e];
        if ((int)(blockIdx.x * 128) >= n) return;
        Bb = w2 + (size_t)e * (size_t)II * H;
    } else { n = T; Bb = sw2; }

    const int row0 = blockIdx.x * 128;
    const int col0 = blockIdx.y * 128;
    const int tid = threadIdx.x;
    const int nv = routed ? min(128, n - row0) : 128;

    if (tid < 128) {
        int gr = row0 + tid;
        int a = -1;
        const __half* p;
        if (!routed) p = g_shh + (size_t)gr * IS;
        else {
            if (gr < n) a = g_alist[off + gr];
            int aa = a >= 0 ? a : g_alist[off];
            p = g_hh + (size_t)aa * II;
        }
        rowptr[tid] = p;
        aidx[tid] = a;
    }
    __syncthreads();

    const int lane = tid & 31, wid = tid >> 5;
    const int wm = wid >> 2, wn = wid & 3;
    const int gg = lane >> 2, t4 = lane & 3;

    float4 bF[8];
    float acc[4][4][4] = {};

    auto cpA = [&](int k0, int s) {
        #pragma unroll
        for (int r = 0; r < 4; r++) {
            int u = tid + 256 * r;
            int m = u >> 3, kq = u & 7;
            cpasync16(sbase + s * ASTG_DA + m * 144 + kq * 16, rowptr[m] + k0 + kq * 8);
        }
    };
    auto ldgB = [&](int k0) {
        #pragma unroll
        for (int r = 0; r < 8; r++) {
            int u = tid + 256 * r;
            int k = u >> 5, ng = u & 31;
            bF[r] = *(const float4*)(Bb + (size_t)(k0 + k) * H + col0 + ng * 4);
        }
    };
    auto stsB = [&](int s) {
        char* B_ = smem + BOFF_D + s * BSTG_D;
        #pragma unroll
        for (int r = 0; r < 8; r++) {
            int u = tid + 256 * r;
            int k = u >> 5, ng = u & 31;
            *(uint2*)(B_ + k * 272 + ng * 8) =
                make_uint2(pk2(bF[r].x, bF[r].y), pk2(bF[r].z, bF[r].w));
        }
    };
    const int lrA = (lane & 7) + ((lane >> 3) & 1) * 8;
    const int lkA = (lane >> 4) * 8;
    const int kBo = (lane & 7) + ((lane >> 3) & 1) * 8;
    const int nBo = (lane >> 4) * 8;
    auto comp = [&](int s) {
        const uint32_t Ab = sbase + s * ASTG_DA;
        const uint32_t Bbs = sbase + BOFF_D + s * BSTG_D;
        if (wm * 64 >= nv) return;
        #pragma unroll
        for (int ks = 0; ks < 4; ks++) {
            const int kh = ks * 16;
            uint32_t af[4][4];
            #pragma unroll
            for (int mt = 0; mt < 4; mt++)
                if (wm * 64 + mt * 16 < nv)
                    ldmx4(af[mt], Ab + (wm * 64 + mt * 16 + lrA) * 144 + (kh + lkA) * 2);
            uint32_t bf[2][4];
            #pragma unroll
            for (int np = 0; np < 2; np++)
                ldmx4t(bf[np], Bbs + (kh + kBo) * 272 + (wn * 32 + np * 16 + nBo) * 2);
            #pragma unroll
            for (int mt = 0; mt < 4; mt++) {
                if (wm * 64 + mt * 16 >= nv) continue;
                #pragma unroll
                for (int nt = 0; nt < 4; nt++)
                    mma16(acc[mt][nt], af[mt], bf[nt >> 1][(nt & 1) * 2], bf[nt >> 1][(nt & 1) * 2 + 1]);
            }
        }
    };

    cpA(0, 0); cp_commit();
    ldgB(0);
    stsB(0);
    cp_wait0();
    __syncthreads();
    for (int c = 0; c < NCr; c++) {
        if (c + 1 < NCr) {
            cpA((c + 1) * 64, (c + 1) & 1); cp_commit();
            ldgB((c + 1) * 64);
        }
        comp(c & 1);
        if (c + 1 < NCr) stsB((c + 1) & 1);
        cp_wait0();
        __syncthreads();
    }

    const float scale = routed ? SCALEF : 1.f;
    #pragma unroll
    for (int mt = 0; mt < 4; mt++) {
        #pragma unroll
        for (int hf = 0; hf < 2; hf++) {
            int r = wm * 64 + mt * 16 + gg + hf * 8;
            float* drow = nullptr;
            if (!routed) drow = Dout + (size_t)(row0 + r) * H + col0;
            else {
                int a = aidx[r];
                if (a >= 0) drow = Dout + (size_t)(a / KSEL) * H + col0;
            }
            if (drow) {
                #pragma unroll
                for (int nt = 0; nt < 4; nt++) {
                    int cc = wn * 32 + nt * 8 + t4 * 2;
                    atomicAdd(drow + cc,     scale * acc[mt][nt][hf * 2]);
                    atomicAdd(drow + cc + 1, scale * acc[mt][nt][hf * 2 + 1]);
                }
            }
        }
    }
}

// ---------------- launch ----------------
extern "C" void kernel_launch(void* const* d_in, const int* in_sizes, int n_in,
                              void* d_out, int out_size) {
    const float* x   = (const float*)d_in[0];
    const float* gw  = (const float*)d_in[1];
    const float* gb  = (const float*)d_in[2];
    const float* w1  = (const float*)d_in[3];
    const float* w2  = (const float*)d_in[4];
    const float* sw1 = (const float*)d_in[5];
    const float* sw2 = (const float*)d_in[6];
    float* out = (float*)d_out;

    cudaFuncSetAttribute(gemm_gateup, cudaFuncAttributeMaxDynamicSharedMemorySize, SMEM_F);
    cudaFuncSetAttribute(gemm_down,   cudaFuncAttributeMaxDynamicSharedMemorySize, SMEM_D);

    xhalf_kernel<<<((T * H / 4) + 255) / 256, 256>>>(x, out);
    router_kernel<<<T, 128>>>(x, gw, gb);
    fill_kernel<<<(NA + 255) / 256, 256>>>();

    // merged gate_up: z<32 routed experts, z==32 shared expert
    gemm_gateup<<<dim3(16, IS / 128, E + 1), 256, SMEM_F>>>(w1, sw1);
    // merged down-proj: all paths atomicAdd into pre-zeroed out
    gemm_down<<<dim3(16, H / 128, E + 1), 256, SMEM_D>>>(w2, sw2, out);
}